// round 1
// baseline (speedup 1.0000x reference)
#include <cuda_runtime.h>
#include <math.h>

#define Bz   4
#define Tt   512
#define Dd   768
#define Hh   8
#define HDim 96
#define Ll   12
#define Vv   50257
#define MR   (Bz*Tt)              // 2048 rows
#define ATT_SCALE 0.10206207261596575f  // 96^-0.5

// ---------------- scratch (device globals; no allocation allowed) ----------------
__device__ float g_x  [MR*Dd];        // residual stream
__device__ float g_h  [MR*Dd];        // ln output
__device__ float g_qkv[MR*3*Dd];
__device__ float g_q  [MR*Dd];        // [B,H,T,HD]
__device__ float g_k  [MR*Dd];        // [B,H,T,HD]
__device__ float g_vt [MR*Dd];        // [B,H,HD,T]  (V transposed)
__device__ float g_s  [(size_t)Bz*Hh*Tt*Tt];  // scores / attn  (33.5 MB)
__device__ float g_o  [MR*Dd];        // attn output in [B,T,D]
__device__ float g_f  [MR*4*Dd];      // ffn intermediate

// ---------------- embedding ----------------
__global__ void embed_k(const int* __restrict__ idx, const float* __restrict__ tok,
                        const float* __restrict__ pos, float* __restrict__ x) {
    int i = blockIdx.x * 256 + threadIdx.x;          // over MR*Dd
    int m = i / Dd, d = i - m * Dd;
    int t = m & (Tt - 1);
    x[i] = tok[(size_t)idx[m] * Dd + d] + pos[t * Dd + d];
}

// ---------------- layernorm (block per row) ----------------
__global__ void ln_k(const float* __restrict__ in, float* __restrict__ out,
                     const float* __restrict__ s, const float* __restrict__ b) {
    int m = blockIdx.x, tid = threadIdx.x;
    const float* row = in + (size_t)m * Dd;
    float x0 = row[tid], x1 = row[tid + 256], x2 = row[tid + 512];
    __shared__ float red[256];
    red[tid] = x0 + x1 + x2;
    __syncthreads();
    #pragma unroll
    for (int st = 128; st > 0; st >>= 1) {
        if (tid < st) red[tid] += red[tid + st];
        __syncthreads();
    }
    float mean = red[0] * (1.0f / Dd);
    __syncthreads();
    float d0 = x0 - mean, d1 = x1 - mean, d2 = x2 - mean;
    red[tid] = d0 * d0 + d1 * d1 + d2 * d2;
    __syncthreads();
    #pragma unroll
    for (int st = 128; st > 0; st >>= 1) {
        if (tid < st) red[tid] += red[tid + st];
        __syncthreads();
    }
    float inv = rsqrtf(red[0] * (1.0f / Dd) + 1e-5f);
    float* orow = out + (size_t)m * Dd;
    orow[tid]       = d0 * inv * s[tid]       + b[tid];
    orow[tid + 256] = d1 * inv * s[tid + 256] + b[tid + 256];
    orow[tid + 512] = d2 * inv * s[tid + 512] + b[tid + 512];
}

// ---------------- qkv split (+ V transpose). Leech rotation skipped:
// K orthogonal => (qK)(kK)^T = qk^T, rotation cancels in attention. ----------------
__global__ void split_k(const float* __restrict__ qkv, float* __restrict__ q,
                        float* __restrict__ k, float* __restrict__ vt) {
    int i = blockIdx.x * 256 + threadIdx.x;          // over MR*3*Dd
    int m = i / (3 * Dd), c = i - m * (3 * Dd);
    int sct = c / Dd;  int r = c - sct * Dd;
    int h = r / HDim;  int hd = r - h * HDim;
    int bb = m / Tt,   t = m - bb * Tt;
    int bh = bb * Hh + h;
    float val = qkv[i];
    if (sct == 0)      q [((size_t)bh * Tt + t) * HDim + hd] = val;
    else if (sct == 1) k [((size_t)bh * Tt + t) * HDim + hd] = val;
    else               vt[((size_t)bh * HDim + hd) * Tt + t] = val;
}

// ---------------- main NT SGEMM: C[M,N] = A[M,K] * B[N,K]^T  (+ epilogue) ----------
// epi: 0 none | 1 +bias | 2 gelu(x+bias) | 3 +resid | 4 +bias+resid
__global__ __launch_bounds__(256) void gemm_k(
    const float* __restrict__ A, const float* __restrict__ Bm, float* __restrict__ C,
    int M, int N, int K,
    const float* __restrict__ bias, const float* __restrict__ resid, int epi) {
    __shared__ float As[16][128];
    __shared__ float Bs[16][128];
    int tid = threadIdx.x;
    int n0 = blockIdx.x * 128, m0 = blockIdx.y * 128;
    int tx = tid & 15, ty = tid >> 4;
    float acc[8][8] = {};
    for (int kt = 0; kt < K; kt += 16) {
        #pragma unroll
        for (int i = 0; i < 2; i++) {
            int f = tid * 2 + i;          // 0..511
            int r = f >> 2, kq = (f & 3) * 4;
            float4 va = *(const float4*)(A + (size_t)(m0 + r) * K + kt + kq);
            As[kq][r] = va.x; As[kq + 1][r] = va.y; As[kq + 2][r] = va.z; As[kq + 3][r] = va.w;
            float4 vb = make_float4(0.f, 0.f, 0.f, 0.f);
            if (n0 + r < N) vb = *(const float4*)(Bm + (size_t)(n0 + r) * K + kt + kq);
            Bs[kq][r] = vb.x; Bs[kq + 1][r] = vb.y; Bs[kq + 2][r] = vb.z; Bs[kq + 3][r] = vb.w;
        }
        __syncthreads();
        #pragma unroll
        for (int kk = 0; kk < 16; kk++) {
            float a[8], bfr[8];
            *(float4*)(a)     = *(const float4*)&As[kk][ty * 8];
            *(float4*)(a + 4) = *(const float4*)&As[kk][ty * 8 + 4];
            *(float4*)(bfr)     = *(const float4*)&Bs[kk][tx * 8];
            *(float4*)(bfr + 4) = *(const float4*)&Bs[kk][tx * 8 + 4];
            #pragma unroll
            for (int i = 0; i < 8; i++)
                #pragma unroll
                for (int j = 0; j < 8; j++)
                    acc[i][j] += a[i] * bfr[j];
        }
        __syncthreads();
    }
    #pragma unroll
    for (int i = 0; i < 8; i++) {
        int m = m0 + ty * 8 + i;
        #pragma unroll
        for (int j = 0; j < 8; j++) {
            int n = n0 + tx * 8 + j;
            if (n < N) {
                float v = acc[i][j];
                if (epi == 1 || epi == 2 || epi == 4) v += bias[n];
                if (epi == 2) v = 0.5f * v * (1.0f + erff(v * 0.70710678118654752f));
                if (epi >= 3) v += resid[(size_t)m * N + n];
                C[(size_t)m * N + n] = v;
            }
        }
    }
}

// ---------------- batched attention NT GEMM ----------------
// mode 0: scores = Q*K^T*scale with causal mask, C at z*T*T (skip fully-masked tiles)
// mode 1: O = P*Vt^T, written into [B,T,D] layout at head h = z%H
__global__ __launch_bounds__(256) void attn_gemm_k(
    const float* __restrict__ A, const float* __restrict__ Bm, float* __restrict__ C,
    int M, int N, int K, long sA, long sB, int mode) {
    int z = blockIdx.z;
    int n0 = blockIdx.x * 128, m0 = blockIdx.y * 128;
    if (mode == 0 && n0 > m0 + 127) return;   // tile entirely above causal diagonal
    A += (size_t)z * sA;
    Bm += (size_t)z * sB;
    __shared__ float As[16][128];
    __shared__ float Bs[16][128];
    int tid = threadIdx.x;
    int tx = tid & 15, ty = tid >> 4;
    float acc[8][8] = {};
    for (int kt = 0; kt < K; kt += 16) {
        #pragma unroll
        for (int i = 0; i < 2; i++) {
            int f = tid * 2 + i;
            int r = f >> 2, kq = (f & 3) * 4;
            float4 va = *(const float4*)(A + (size_t)(m0 + r) * K + kt + kq);
            As[kq][r] = va.x; As[kq + 1][r] = va.y; As[kq + 2][r] = va.z; As[kq + 3][r] = va.w;
            float4 vb = make_float4(0.f, 0.f, 0.f, 0.f);
            if (n0 + r < N) vb = *(const float4*)(Bm + (size_t)(n0 + r) * K + kt + kq);
            Bs[kq][r] = vb.x; Bs[kq + 1][r] = vb.y; Bs[kq + 2][r] = vb.z; Bs[kq + 3][r] = vb.w;
        }
        __syncthreads();
        #pragma unroll
        for (int kk = 0; kk < 16; kk++) {
            float a[8], bfr[8];
            *(float4*)(a)     = *(const float4*)&As[kk][ty * 8];
            *(float4*)(a + 4) = *(const float4*)&As[kk][ty * 8 + 4];
            *(float4*)(bfr)     = *(const float4*)&Bs[kk][tx * 8];
            *(float4*)(bfr + 4) = *(const float4*)&Bs[kk][tx * 8 + 4];
            #pragma unroll
            for (int i = 0; i < 8; i++)
                #pragma unroll
                for (int j = 0; j < 8; j++)
                    acc[i][j] += a[i] * bfr[j];
        }
        __syncthreads();
    }
    if (mode == 0) {
        float* Cb = C + (size_t)z * Tt * Tt;
        #pragma unroll
        for (int i = 0; i < 8; i++) {
            int q = m0 + ty * 8 + i;
            #pragma unroll
            for (int j = 0; j < 8; j++) {
                int k = n0 + tx * 8 + j;
                Cb[(size_t)q * Tt + k] = (k <= q) ? acc[i][j] * ATT_SCALE : -1e30f;
            }
        }
    } else {
        int bb = z / Hh, h = z - bb * Hh;
        float* Cb = C + (size_t)bb * Tt * Dd + h * HDim;
        #pragma unroll
        for (int i = 0; i < 8; i++) {
            int m = m0 + ty * 8 + i;
            #pragma unroll
            for (int j = 0; j < 8; j++) {
                int n = n0 + tx * 8 + j;
                if (n < N) Cb[(size_t)m * Dd + n] = acc[i][j];
            }
        }
    }
}

// ---------------- causal row softmax (block per (bh,q) row) ----------------
__global__ void softmax_k(float* __restrict__ S) {
    int bid = blockIdx.x;
    int q = bid & (Tt - 1);
    int bh = bid >> 9;
    float* row = S + ((size_t)bh * Tt + q) * Tt;
    int len = q + 1;
    int tid = threadIdx.x;   // 128
    __shared__ float red[128];
    float mx = -1e30f;
    for (int k = tid; k < len; k += 128) mx = fmaxf(mx, row[k]);
    red[tid] = mx;
    __syncthreads();
    #pragma unroll
    for (int st = 64; st > 0; st >>= 1) {
        if (tid < st) red[tid] = fmaxf(red[tid], red[tid + st]);
        __syncthreads();
    }
    mx = red[0];
    __syncthreads();
    float sum = 0.f;
    for (int k = tid; k < len; k += 128) {
        float e = expf(row[k] - mx);
        row[k] = e;
        sum += e;
    }
    red[tid] = sum;
    __syncthreads();
    #pragma unroll
    for (int st = 64; st > 0; st >>= 1) {
        if (tid < st) red[tid] += red[tid + st];
        __syncthreads();
    }
    float inv = 1.0f / red[0];
    for (int k = tid; k < len; k += 128) row[k] *= inv;
    for (int k = len + tid; k < Tt; k += 128) row[k] = 0.f;   // zero masked tail (read by O GEMM)
}

// ---------------- launch ----------------
extern "C" void kernel_launch(void* const* d_in, const int* in_sizes, int n_in,
                              void* d_out, int out_size) {
    const int*   idx    = (const int*)  d_in[0];
    const float* tok    = (const float*)d_in[1];
    const float* pos    = (const float*)d_in[2];
    const float* ln1_s  = (const float*)d_in[3];
    const float* ln1_b  = (const float*)d_in[4];
    const float* qkv_w  = (const float*)d_in[5];
    const float* out_w  = (const float*)d_in[6];
    const float* ln2_s  = (const float*)d_in[7];
    const float* ln2_b  = (const float*)d_in[8];
    const float* ffn_w1 = (const float*)d_in[9];
    const float* ffn_b1 = (const float*)d_in[10];
    const float* ffn_w2 = (const float*)d_in[11];
    const float* ffn_b2 = (const float*)d_in[12];
    const float* fn_s   = (const float*)d_in[13];
    const float* fn_b   = (const float*)d_in[14];
    const float* head_w = (const float*)d_in[15];

    float* logits = (float*)d_out;
    float* hidden = logits + (size_t)Bz * Tt * Vv;

    float *x, *h, *qkv, *q, *k, *vt, *s, *o, *f;
    cudaGetSymbolAddress((void**)&x,   g_x);
    cudaGetSymbolAddress((void**)&h,   g_h);
    cudaGetSymbolAddress((void**)&qkv, g_qkv);
    cudaGetSymbolAddress((void**)&q,   g_q);
    cudaGetSymbolAddress((void**)&k,   g_k);
    cudaGetSymbolAddress((void**)&vt,  g_vt);
    cudaGetSymbolAddress((void**)&s,   g_s);
    cudaGetSymbolAddress((void**)&o,   g_o);
    cudaGetSymbolAddress((void**)&f,   g_f);

    embed_k<<<(MR * Dd) / 256, 256>>>(idx, tok, pos, x);

    for (int l = 0; l < Ll; l++) {
        ln_k<<<MR, 256>>>(x, h, ln1_s + l * Dd, ln1_b + l * Dd);
        gemm_k<<<dim3(18, 16), 256>>>(h, qkv_w + (size_t)l * 3 * Dd * Dd, qkv,
                                      MR, 3 * Dd, Dd, nullptr, nullptr, 0);
        split_k<<<(MR * 3 * Dd) / 256, 256>>>(qkv, q, k, vt);
        attn_gemm_k<<<dim3(4, 4, Bz * Hh), 256>>>(q, k, s, Tt, Tt, HDim,
                                                  (long)Tt * HDim, (long)Tt * HDim, 0);
        softmax_k<<<Bz * Hh * Tt, 128>>>(s);
        attn_gemm_k<<<dim3(1, 4, Bz * Hh), 256>>>(s, vt, o, Tt, HDim, Tt,
                                                  (long)Tt * Tt, (long)HDim * Tt, 1);
        gemm_k<<<dim3(6, 16), 256>>>(o, out_w + (size_t)l * Dd * Dd, x,
                                     MR, Dd, Dd, nullptr, x, 3);
        ln_k<<<MR, 256>>>(x, h, ln2_s + l * Dd, ln2_b + l * Dd);
        gemm_k<<<dim3(24, 16), 256>>>(h, ffn_w1 + (size_t)l * 4 * Dd * Dd, f,
                                      MR, 4 * Dd, Dd, ffn_b1 + l * 4 * Dd, nullptr, 2);
        gemm_k<<<dim3(6, 16), 256>>>(f, ffn_w2 + (size_t)l * Dd * 4 * Dd, x,
                                     MR, Dd, 4 * Dd, ffn_b2 + l * Dd, x, 4);
    }

    ln_k<<<MR, 256>>>(x, hidden, fn_s, fn_b);
    gemm_k<<<dim3(393, 16), 256>>>(hidden, head_w, logits,
                                   MR, Vv, Dd, nullptr, nullptr, 0);
}

// round 3
// speedup vs baseline: 2.3106x; 2.3106x over previous
#include <cuda_runtime.h>
#include <cuda_bf16.h>
#include <math.h>
#include <stdint.h>

#define Bz   4
#define Tt   512
#define Dd   768
#define Hh   8
#define HDim 96
#define Ll   12
#define Vv   50257
#define MR   (Bz*Tt)
#define ATT_SCALE 0.10206207261596575f

__device__ __forceinline__ uint32_t smem_u32(const void* p) {
    uint32_t a;
    asm("{ .reg .u64 t; cvta.to.shared.u64 t, %1; cvt.u32.u64 %0, t; }" : "=r"(a) : "l"(p));
    return a;
}

// ---------------- scratch (device globals) ----------------
__device__ float g_x  [MR*Dd];
__device__ float g_qkv[MR*3*Dd];
__device__ float g_q  [MR*Dd];
__device__ float g_k  [MR*Dd];
__device__ float g_vt [MR*Dd];
__device__ float g_s  [(size_t)Bz*Hh*Tt*Tt];
__device__ __align__(16) __nv_bfloat16 g_hhi[MR*Dd],   g_hlo[MR*Dd];
__device__ __align__(16) __nv_bfloat16 g_ohi[MR*Dd],   g_olo[MR*Dd];
__device__ __align__(16) __nv_bfloat16 g_fhi[MR*4*Dd], g_flo[MR*4*Dd];
__device__ __align__(16) __nv_bfloat16 g_wqkv_hi[(size_t)Ll*3*Dd*Dd], g_wqkv_lo[(size_t)Ll*3*Dd*Dd];
__device__ __align__(16) __nv_bfloat16 g_wout_hi[(size_t)Ll*Dd*Dd],   g_wout_lo[(size_t)Ll*Dd*Dd];
__device__ __align__(16) __nv_bfloat16 g_wf1_hi [(size_t)Ll*4*Dd*Dd], g_wf1_lo [(size_t)Ll*4*Dd*Dd];
__device__ __align__(16) __nv_bfloat16 g_wf2_hi [(size_t)Ll*4*Dd*Dd], g_wf2_lo [(size_t)Ll*4*Dd*Dd];
__device__ __align__(16) __nv_bfloat16 g_wh_hi  [(size_t)Vv*Dd],      g_wh_lo  [(size_t)Vv*Dd];

// ---------------- weight fp32 -> bf16 hi/lo split ----------------
__global__ void cvt_k(const float* __restrict__ w, __nv_bfloat16* __restrict__ hi,
                      __nv_bfloat16* __restrict__ lo, size_t n) {
    size_t i = (size_t)blockIdx.x * 256 + threadIdx.x;
    if (i >= n) return;
    float v = w[i];
    __nv_bfloat16 h = __float2bfloat16(v);
    hi[i] = h;
    lo[i] = __float2bfloat16(v - __bfloat162float(h));
}

// ---------------- embedding ----------------
__global__ void embed_k(const int* __restrict__ idx, const float* __restrict__ tok,
                        const float* __restrict__ pos, float* __restrict__ x) {
    int i = blockIdx.x * 256 + threadIdx.x;
    int m = i / Dd, d = i - m * Dd;
    int t = m & (Tt - 1);
    x[i] = tok[(size_t)idx[m] * Dd + d] + pos[t * Dd + d];
}

// ---------------- layernorm -> bf16 hi/lo (+ optional fp32) ----------------
__global__ void ln_bf16_k(const float* __restrict__ in, const float* __restrict__ s,
                          const float* __restrict__ b, __nv_bfloat16* __restrict__ ohi,
                          __nv_bfloat16* __restrict__ olo, float* __restrict__ ofp) {
    int m = blockIdx.x, tid = threadIdx.x;
    const float* row = in + (size_t)m * Dd;
    float x0 = row[tid], x1 = row[tid + 256], x2 = row[tid + 512];
    __shared__ float red[256];
    red[tid] = x0 + x1 + x2;
    __syncthreads();
    #pragma unroll
    for (int st = 128; st > 0; st >>= 1) { if (tid < st) red[tid] += red[tid + st]; __syncthreads(); }
    float mean = red[0] * (1.0f / Dd);
    __syncthreads();
    float d0 = x0 - mean, d1 = x1 - mean, d2 = x2 - mean;
    red[tid] = d0 * d0 + d1 * d1 + d2 * d2;
    __syncthreads();
    #pragma unroll
    for (int st = 128; st > 0; st >>= 1) { if (tid < st) red[tid] += red[tid + st]; __syncthreads(); }
    float inv = rsqrtf(red[0] * (1.0f / Dd) + 1e-5f);
    size_t base = (size_t)m * Dd;
    #pragma unroll
    for (int q = 0; q < 3; q++) {
        int c = tid + q * 256;
        float dv = (q == 0 ? d0 : (q == 1 ? d1 : d2));
        float v = dv * inv * s[c] + b[c];
        __nv_bfloat16 h = __float2bfloat16(v);
        ohi[base + c] = h;
        olo[base + c] = __float2bfloat16(v - __bfloat162float(h));
        if (ofp) ofp[base + c] = v;
    }
}

// ---------------- qkv split (Leech rotation cancels: K orthogonal) ----------------
__global__ void split_k(const float* __restrict__ qkv, float* __restrict__ q,
                        float* __restrict__ k, float* __restrict__ vt) {
    int i = blockIdx.x * 256 + threadIdx.x;
    int m = i / (3 * Dd), c = i - m * (3 * Dd);
    int sct = c / Dd;  int r = c - sct * Dd;
    int h = r / HDim;  int hd = r - h * HDim;
    int bb = m / Tt,   t = m - bb * Tt;
    int bh = bb * Hh + h;
    float val = qkv[i];
    if (sct == 0)      q [((size_t)bh * Tt + t) * HDim + hd] = val;
    else if (sct == 1) k [((size_t)bh * Tt + t) * HDim + hd] = val;
    else               vt[((size_t)bh * HDim + hd) * Tt + t] = val;
}

// ---------------- HMMA GEMM: C[M,N] = A[M,K]*B[N,K]^T, bf16x3 split, fp32 acc ----
// CTA 128x128, 8 warps (2x4), warp 64x32, K-chunk 64, cp.async double buffer.
#define ROWB 144
#define OPB  (128*ROWB)      // 18432
#define STG  (4*OPB)         // 73728
#define SMEM_MM (2*STG)      // 147456

__device__ __forceinline__ void ldsm4(uint32_t& r0, uint32_t& r1, uint32_t& r2, uint32_t& r3,
                                      uint32_t addr) {
    asm volatile("ldmatrix.sync.aligned.m8n8.x4.shared.b16 {%0,%1,%2,%3}, [%4];"
                 : "=r"(r0), "=r"(r1), "=r"(r2), "=r"(r3) : "r"(addr));
}
__device__ __forceinline__ void mma16816(float* d, const uint32_t* a, const uint32_t* b) {
    asm volatile("mma.sync.aligned.m16n8k16.row.col.f32.bf16.bf16.f32 "
                 "{%0,%1,%2,%3}, {%4,%5,%6,%7}, {%8,%9}, {%0,%1,%2,%3};"
                 : "+f"(d[0]), "+f"(d[1]), "+f"(d[2]), "+f"(d[3])
                 : "r"(a[0]), "r"(a[1]), "r"(a[2]), "r"(a[3]), "r"(b[0]), "r"(b[1]));
}

__global__ __launch_bounds__(256) void gemm_mm(
    const __nv_bfloat16* __restrict__ Ahi, const __nv_bfloat16* __restrict__ Alo,
    const __nv_bfloat16* __restrict__ Bhi, const __nv_bfloat16* __restrict__ Blo,
    int N, int K,
    const float* __restrict__ bias, const float* __restrict__ resid,
    float* __restrict__ Cf, __nv_bfloat16* __restrict__ Chi, __nv_bfloat16* __restrict__ Clo,
    int do_gelu)
{
    extern __shared__ char smem[];
    uint32_t sb = smem_u32(smem);
    int tid = threadIdx.x, wid = tid >> 5, lane = tid & 31;
    int wm = wid >> 2, wn = wid & 3;
    int m0 = blockIdx.y * 128, n0 = blockIdx.x * 128;

    auto load_chunk = [&](int c) {
        int kt = c << 6;
        uint32_t st = sb + (c & 1) * STG;
        #pragma unroll
        for (int o = 0; o < 16; o++) {
            int flat = o * 256 + tid;
            int op = flat >> 10, wi = flat & 1023;
            int row = wi >> 3, c16 = wi & 7;
            uint32_t dst = st + op * OPB + row * ROWB + c16 * 16;
            const __nv_bfloat16* src;
            if (op < 2) {
                src = (op == 0 ? Ahi : Alo) + (size_t)(m0 + row) * K + kt + c16 * 8;
            } else {
                int r = n0 + row; if (r >= N) r = N - 1;
                src = (op == 2 ? Bhi : Blo) + (size_t)r * K + kt + c16 * 8;
            }
            asm volatile("cp.async.cg.shared.global [%0], [%1], 16;" :: "r"(dst), "l"(src));
        }
        asm volatile("cp.async.commit_group;" ::: "memory");
    };

    float acc[4][4][4] = {};
    int nc = K >> 6;

    load_chunk(0);
    load_chunk(1);

    for (int c = 0; c < nc; c++) {
        if (c + 1 < nc) asm volatile("cp.async.wait_group 1;" ::: "memory");
        else            asm volatile("cp.async.wait_group 0;" ::: "memory");
        __syncthreads();
        uint32_t st = sb + (c & 1) * STG;
        uint32_t a_row = (uint32_t)(wm * 64 + (lane & 15)) * ROWB + (lane >> 4) * 16;
        uint32_t b_row = (uint32_t)(wn * 32 + (lane & 7) + ((lane >> 4) & 1) * 8) * ROWB
                       + ((lane >> 3) & 1) * 16;
        #pragma unroll
        for (int kk = 0; kk < 4; kk++) {
            uint32_t ah[4][4], al[4][4], bh[4][2], bl[4][2];
            #pragma unroll
            for (int mt = 0; mt < 4; mt++) {
                uint32_t ad = st + a_row + mt * (16 * ROWB) + kk * 32;
                ldsm4(ah[mt][0], ah[mt][1], ah[mt][2], ah[mt][3], ad);
                ldsm4(al[mt][0], al[mt][1], al[mt][2], al[mt][3], ad + OPB);
            }
            #pragma unroll
            for (int np = 0; np < 2; np++) {
                uint32_t bd = st + 2 * OPB + b_row + np * (16 * ROWB) + kk * 32;
                ldsm4(bh[np*2][0], bh[np*2][1], bh[np*2+1][0], bh[np*2+1][1], bd);
                ldsm4(bl[np*2][0], bl[np*2][1], bl[np*2+1][0], bl[np*2+1][1], bd + OPB);
            }
            #pragma unroll
            for (int mt = 0; mt < 4; mt++)
                #pragma unroll
                for (int nt = 0; nt < 4; nt++)
                    mma16816(acc[mt][nt], ah[mt], bh[nt]);
            #pragma unroll
            for (int mt = 0; mt < 4; mt++)
                #pragma unroll
                for (int nt = 0; nt < 4; nt++)
                    mma16816(acc[mt][nt], ah[mt], bl[nt]);
            #pragma unroll
            for (int mt = 0; mt < 4; mt++)
                #pragma unroll
                for (int nt = 0; nt < 4; nt++)
                    mma16816(acc[mt][nt], al[mt], bh[nt]);
        }
        __syncthreads();
        if (c + 2 < nc) load_chunk(c + 2);
    }

    // epilogue
    #pragma unroll
    for (int mt = 0; mt < 4; mt++) {
        #pragma unroll
        for (int nt = 0; nt < 4; nt++) {
            int mbase = m0 + wm * 64 + mt * 16 + (lane >> 2);
            int nbase = n0 + wn * 32 + nt * 8 + (lane & 3) * 2;
            #pragma unroll
            for (int hrow = 0; hrow < 2; hrow++) {
                int m = mbase + hrow * 8;
                #pragma unroll
                for (int jj = 0; jj < 2; jj++) {
                    int n = nbase + jj;
                    if (n < N) {
                        float v = acc[mt][nt][hrow * 2 + jj];
                        if (bias) v += bias[n];
                        if (do_gelu) v = 0.5f * v * (1.0f + erff(v * 0.70710678118654752f));
                        size_t ix = (size_t)m * N + n;
                        if (resid) v += resid[ix];
                        if (Cf) Cf[ix] = v;
                        if (Chi) {
                            __nv_bfloat16 hv = __float2bfloat16(v);
                            Chi[ix] = hv;
                            Clo[ix] = __float2bfloat16(v - __bfloat162float(hv));
                        }
                    }
                }
            }
        }
    }
}

// ---------------- batched attention NT GEMM (fp32) ----------------
__global__ __launch_bounds__(256) void attn_gemm_k(
    const float* __restrict__ A, const float* __restrict__ Bm, float* __restrict__ C,
    __nv_bfloat16* __restrict__ Ohi, __nv_bfloat16* __restrict__ Olo,
    int N, int K, long sA, long sB, int mode) {
    int z = blockIdx.z;
    int n0 = blockIdx.x * 128, m0 = blockIdx.y * 128;
    if (mode == 0 && n0 > m0 + 127) return;
    A += (size_t)z * sA;
    Bm += (size_t)z * sB;
    __shared__ float As[16][128];
    __shared__ float Bs[16][128];
    int tid = threadIdx.x;
    int tx = tid & 15, ty = tid >> 4;
    float acc[8][8] = {};
    for (int kt = 0; kt < K; kt += 16) {
        #pragma unroll
        for (int i = 0; i < 2; i++) {
            int f = tid * 2 + i;
            int r = f >> 2, kq = (f & 3) * 4;
            float4 va = *(const float4*)(A + (size_t)(m0 + r) * K + kt + kq);
            As[kq][r] = va.x; As[kq + 1][r] = va.y; As[kq + 2][r] = va.z; As[kq + 3][r] = va.w;
            float4 vb = make_float4(0.f, 0.f, 0.f, 0.f);
            if (n0 + r < N) vb = *(const float4*)(Bm + (size_t)(n0 + r) * K + kt + kq);
            Bs[kq][r] = vb.x; Bs[kq + 1][r] = vb.y; Bs[kq + 2][r] = vb.z; Bs[kq + 3][r] = vb.w;
        }
        __syncthreads();
        #pragma unroll
        for (int kk = 0; kk < 16; kk++) {
            float a[8], bfr[8];
            *(float4*)(a)       = *(const float4*)&As[kk][ty * 8];
            *(float4*)(a + 4)   = *(const float4*)&As[kk][ty * 8 + 4];
            *(float4*)(bfr)     = *(const float4*)&Bs[kk][tx * 8];
            *(float4*)(bfr + 4) = *(const float4*)&Bs[kk][tx * 8 + 4];
            #pragma unroll
            for (int i = 0; i < 8; i++)
                #pragma unroll
                for (int j = 0; j < 8; j++)
                    acc[i][j] += a[i] * bfr[j];
        }
        __syncthreads();
    }
    if (mode == 0) {
        float* Cb = C + (size_t)z * Tt * Tt;
        #pragma unroll
        for (int i = 0; i < 8; i++) {
            int q = m0 + ty * 8 + i;
            #pragma unroll
            for (int j = 0; j < 8; j++) {
                int k = n0 + tx * 8 + j;
                Cb[(size_t)q * Tt + k] = (k <= q) ? acc[i][j] * ATT_SCALE : -1e30f;
            }
        }
    } else {
        int bb = z / Hh, h = z - bb * Hh;
        size_t base = (size_t)bb * Tt * Dd + h * HDim;
        #pragma unroll
        for (int i = 0; i < 8; i++) {
            int m = m0 + ty * 8 + i;
            #pragma unroll
            for (int j = 0; j < 8; j++) {
                int n = n0 + tx * 8 + j;
                if (n < N) {
                    float v = acc[i][j];
                    size_t ix = base + (size_t)m * Dd + n;
                    __nv_bfloat16 hv = __float2bfloat16(v);
                    Ohi[ix] = hv;
                    Olo[ix] = __float2bfloat16(v - __bfloat162float(hv));
                }
            }
        }
    }
}

// ---------------- causal row softmax ----------------
__global__ void softmax_k(float* __restrict__ S) {
    int bid = blockIdx.x;
    int q = bid & (Tt - 1);
    int bh = bid >> 9;
    float* row = S + ((size_t)bh * Tt + q) * Tt;
    int len = q + 1;
    int tid = threadIdx.x;
    __shared__ float red[128];
    float mx = -1e30f;
    for (int k = tid; k < len; k += 128) mx = fmaxf(mx, row[k]);
    red[tid] = mx;
    __syncthreads();
    #pragma unroll
    for (int st = 64; st > 0; st >>= 1) { if (tid < st) red[tid] = fmaxf(red[tid], red[tid + st]); __syncthreads(); }
    mx = red[0];
    __syncthreads();
    float sum = 0.f;
    for (int k = tid; k < len; k += 128) { float e = expf(row[k] - mx); row[k] = e; sum += e; }
    red[tid] = sum;
    __syncthreads();
    #pragma unroll
    for (int st = 64; st > 0; st >>= 1) { if (tid < st) red[tid] += red[tid + st]; __syncthreads(); }
    float inv = 1.0f / red[0];
    for (int k = tid; k < len; k += 128) row[k] *= inv;
    for (int k = len + tid; k < Tt; k += 128) row[k] = 0.f;
}

// ---------------- launch ----------------
extern "C" void kernel_launch(void* const* d_in, const int* in_sizes, int n_in,
                              void* d_out, int out_size) {
    const int*   idx    = (const int*)  d_in[0];
    const float* tok    = (const float*)d_in[1];
    const float* pos    = (const float*)d_in[2];
    const float* ln1_s  = (const float*)d_in[3];
    const float* ln1_b  = (const float*)d_in[4];
    const float* qkv_w  = (const float*)d_in[5];
    const float* out_w  = (const float*)d_in[6];
    const float* ln2_s  = (const float*)d_in[7];
    const float* ln2_b  = (const float*)d_in[8];
    const float* ffn_w1 = (const float*)d_in[9];
    const float* ffn_b1 = (const float*)d_in[10];
    const float* ffn_w2 = (const float*)d_in[11];
    const float* ffn_b2 = (const float*)d_in[12];
    const float* fn_s   = (const float*)d_in[13];
    const float* fn_b   = (const float*)d_in[14];
    const float* head_w = (const float*)d_in[15];

    float* logits = (float*)d_out;
    float* hidden = logits + (size_t)Bz * Tt * Vv;

    float *x, *qkv, *q, *k, *vt, *s;
    __nv_bfloat16 *hhi, *hlo, *ohi, *olo, *fhi, *flo;
    __nv_bfloat16 *wqh, *wql, *woh, *wol, *w1h, *w1l, *w2h, *w2l, *whh, *whl;
    cudaGetSymbolAddress((void**)&x,   g_x);
    cudaGetSymbolAddress((void**)&qkv, g_qkv);
    cudaGetSymbolAddress((void**)&q,   g_q);
    cudaGetSymbolAddress((void**)&k,   g_k);
    cudaGetSymbolAddress((void**)&vt,  g_vt);
    cudaGetSymbolAddress((void**)&s,   g_s);
    cudaGetSymbolAddress((void**)&hhi, g_hhi);  cudaGetSymbolAddress((void**)&hlo, g_hlo);
    cudaGetSymbolAddress((void**)&ohi, g_ohi);  cudaGetSymbolAddress((void**)&olo, g_olo);
    cudaGetSymbolAddress((void**)&fhi, g_fhi);  cudaGetSymbolAddress((void**)&flo, g_flo);
    cudaGetSymbolAddress((void**)&wqh, g_wqkv_hi); cudaGetSymbolAddress((void**)&wql, g_wqkv_lo);
    cudaGetSymbolAddress((void**)&woh, g_wout_hi); cudaGetSymbolAddress((void**)&wol, g_wout_lo);
    cudaGetSymbolAddress((void**)&w1h, g_wf1_hi);  cudaGetSymbolAddress((void**)&w1l, g_wf1_lo);
    cudaGetSymbolAddress((void**)&w2h, g_wf2_hi);  cudaGetSymbolAddress((void**)&w2l, g_wf2_lo);
    cudaGetSymbolAddress((void**)&whh, g_wh_hi);   cudaGetSymbolAddress((void**)&whl, g_wh_lo);

    cudaFuncSetAttribute(gemm_mm, cudaFuncAttributeMaxDynamicSharedMemorySize, SMEM_MM);

    {
        size_t n1 = (size_t)Ll * 3 * Dd * Dd;
        size_t n2 = (size_t)Ll * Dd * Dd;
        size_t n3 = (size_t)Ll * 4 * Dd * Dd;
        size_t n5 = (size_t)Vv * Dd;
        cvt_k<<<(unsigned)((n1 + 255) / 256), 256>>>(qkv_w,  wqh, wql, n1);
        cvt_k<<<(unsigned)((n2 + 255) / 256), 256>>>(out_w,  woh, wol, n2);
        cvt_k<<<(unsigned)((n3 + 255) / 256), 256>>>(ffn_w1, w1h, w1l, n3);
        cvt_k<<<(unsigned)((n3 + 255) / 256), 256>>>(ffn_w2, w2h, w2l, n3);
        cvt_k<<<(unsigned)((n5 + 255) / 256), 256>>>(head_w, whh, whl, n5);
    }

    embed_k<<<(MR * Dd) / 256, 256>>>(idx, tok, pos, x);

    for (int l = 0; l < Ll; l++) {
        ln_bf16_k<<<MR, 256>>>(x, ln1_s + l * Dd, ln1_b + l * Dd, hhi, hlo, nullptr);
        gemm_mm<<<dim3(18, 16), 256, SMEM_MM>>>(hhi, hlo, wqh + (size_t)l * 3 * Dd * Dd,
                                                wql + (size_t)l * 3 * Dd * Dd,
                                                3 * Dd, Dd, nullptr, nullptr, qkv, nullptr, nullptr, 0);
        split_k<<<(MR * 3 * Dd) / 256, 256>>>(qkv, q, k, vt);
        attn_gemm_k<<<dim3(4, 4, Bz * Hh), 256>>>(q, k, s, nullptr, nullptr, Tt, HDim,
                                                  (long)Tt * HDim, (long)Tt * HDim, 0);
        softmax_k<<<Bz * Hh * Tt, 128>>>(s);
        attn_gemm_k<<<dim3(1, 4, Bz * Hh), 256>>>(s, vt, nullptr, ohi, olo, HDim, Tt,
                                                  (long)Tt * Tt, (long)HDim * Tt, 1);
        gemm_mm<<<dim3(6, 16), 256, SMEM_MM>>>(ohi, olo, woh + (size_t)l * Dd * Dd,
                                               wol + (size_t)l * Dd * Dd,
                                               Dd, Dd, nullptr, x, x, nullptr, nullptr, 0);
        ln_bf16_k<<<MR, 256>>>(x, ln2_s + l * Dd, ln2_b + l * Dd, hhi, hlo, nullptr);
        gemm_mm<<<dim3(24, 16), 256, SMEM_MM>>>(hhi, hlo, w1h + (size_t)l * 4 * Dd * Dd,
                                                w1l + (size_t)l * 4 * Dd * Dd,
                                                4 * Dd, Dd, ffn_b1 + l * 4 * Dd, nullptr,
                                                nullptr, fhi, flo, 1);
        gemm_mm<<<dim3(6, 16), 256, SMEM_MM>>>(fhi, flo, w2h + (size_t)l * 4 * Dd * Dd,
                                               w2l + (size_t)l * 4 * Dd * Dd,
                                               Dd, 4 * Dd, ffn_b2 + l * Dd, x, x, nullptr, nullptr, 0);
    }

    ln_bf16_k<<<MR, 256>>>(x, fn_s, fn_b, hhi, hlo, hidden);
    gemm_mm<<<dim3(393, 16), 256, SMEM_MM>>>(hhi, hlo, whh, whl,
                                             Vv, Dd, nullptr, nullptr, logits, nullptr, nullptr, 0);
}

// round 4
// speedup vs baseline: 3.9794x; 1.7222x over previous
#include <cuda_runtime.h>
#include <cuda_fp16.h>
#include <math.h>
#include <stdint.h>

#define Bz   4
#define Tt   512
#define Dd   768
#define Hh   8
#define HDim 96
#define Ll   12
#define Vv   50257
#define MR   (Bz*Tt)
#define ATT_SCALE 0.10206207261596575f

__device__ __forceinline__ uint32_t smem_u32(const void* p) {
    uint32_t a;
    asm("{ .reg .u64 t; cvta.to.shared.u64 t, %1; cvt.u32.u64 %0, t; }" : "=r"(a) : "l"(p));
    return a;
}

// ---------------- scratch (device globals) ----------------
__device__ float g_x [MR*Dd];
__device__ float g_q [MR*Dd];        // [B,H,T,HD]
__device__ float g_k [MR*Dd];
__device__ float g_vt[MR*Dd];        // [B,H,HD,T]
__device__ float g_s [(size_t)Bz*Hh*Tt*Tt];
__device__ __align__(16) __half g_h16[MR*Dd];
__device__ __align__(16) __half g_o16[MR*Dd];
__device__ __align__(16) __half g_f16[MR*4*Dd];
__device__ __align__(16) __half g_wq[(size_t)Ll*3*Dd*Dd];
__device__ __align__(16) __half g_wo[(size_t)Ll*Dd*Dd];
__device__ __align__(16) __half g_w1[(size_t)Ll*4*Dd*Dd];
__device__ __align__(16) __half g_w2[(size_t)Ll*4*Dd*Dd];
__device__ __align__(16) __half g_wh[(size_t)Vv*Dd];

// ---------------- weight fp32 -> fp16 (vectorized) ----------------
__global__ void cvt_k(const float* __restrict__ w, __half* __restrict__ o, size_t n4) {
    size_t i = (size_t)blockIdx.x * 256 + threadIdx.x;
    if (i >= n4) return;
    float4 v = ((const float4*)w)[i];
    __half2 a = __floats2half2_rn(v.x, v.y);
    __half2 b = __floats2half2_rn(v.z, v.w);
    ((__half2*)o)[i * 2]     = a;
    ((__half2*)o)[i * 2 + 1] = b;
}

// ---------------- embedding ----------------
__global__ void embed_k(const int* __restrict__ idx, const float* __restrict__ tok,
                        const float* __restrict__ pos, float* __restrict__ x) {
    int i = blockIdx.x * 256 + threadIdx.x;
    int m = i / Dd, d = i - m * Dd;
    int t = m & (Tt - 1);
    x[i] = tok[(size_t)idx[m] * Dd + d] + pos[t * Dd + d];
}

// ---------------- layernorm -> fp16 (+ optional fp32) ----------------
__global__ void ln_k(const float* __restrict__ in, const float* __restrict__ s,
                     const float* __restrict__ b, __half* __restrict__ oh,
                     float* __restrict__ ofp) {
    int m = blockIdx.x, tid = threadIdx.x;
    const float* row = in + (size_t)m * Dd;
    float x0 = row[tid], x1 = row[tid + 256], x2 = row[tid + 512];
    __shared__ float red[256];
    red[tid] = x0 + x1 + x2;
    __syncthreads();
    #pragma unroll
    for (int st = 128; st > 0; st >>= 1) { if (tid < st) red[tid] += red[tid + st]; __syncthreads(); }
    float mean = red[0] * (1.0f / Dd);
    __syncthreads();
    float d0 = x0 - mean, d1 = x1 - mean, d2 = x2 - mean;
    red[tid] = d0 * d0 + d1 * d1 + d2 * d2;
    __syncthreads();
    #pragma unroll
    for (int st = 128; st > 0; st >>= 1) { if (tid < st) red[tid] += red[tid + st]; __syncthreads(); }
    float inv = rsqrtf(red[0] * (1.0f / Dd) + 1e-5f);
    size_t base = (size_t)m * Dd;
    #pragma unroll
    for (int q = 0; q < 3; q++) {
        int c = tid + q * 256;
        float dv = (q == 0 ? d0 : (q == 1 ? d1 : d2));
        float v = dv * inv * s[c] + b[c];
        oh[base + c] = __float2half(v);
        if (ofp) ofp[base + c] = v;
    }
}

// ---------------- HMMA fp16 GEMM: C[M,N] = A[M,K]*B[N,K]^T, fp32 acc ----------
// CTA 128x128, 8 warps (2x4), warp 64x32, K-chunk 64, cp.async double buffer.
// mode: 0 normal | 1 gelu(bias) | 2 qkv split scatter
#define ROWB 144
#define OPB  (128*ROWB)
#define STG  (2*OPB)
#define SMEM_MM (2*STG)      // 73728

__device__ __forceinline__ void ldsm4(uint32_t& r0, uint32_t& r1, uint32_t& r2, uint32_t& r3,
                                      uint32_t addr) {
    asm volatile("ldmatrix.sync.aligned.m8n8.x4.shared.b16 {%0,%1,%2,%3}, [%4];"
                 : "=r"(r0), "=r"(r1), "=r"(r2), "=r"(r3) : "r"(addr));
}
__device__ __forceinline__ void mma16816(float* d, const uint32_t* a, const uint32_t* b) {
    asm volatile("mma.sync.aligned.m16n8k16.row.col.f32.f16.f16.f32 "
                 "{%0,%1,%2,%3}, {%4,%5,%6,%7}, {%8,%9}, {%0,%1,%2,%3};"
                 : "+f"(d[0]), "+f"(d[1]), "+f"(d[2]), "+f"(d[3])
                 : "r"(a[0]), "r"(a[1]), "r"(a[2]), "r"(a[3]), "r"(b[0]), "r"(b[1]));
}

__global__ __launch_bounds__(256, 2) void gemm_mm(
    const __half* __restrict__ A, const __half* __restrict__ Bm,
    int N, int K,
    const float* __restrict__ bias, const float* __restrict__ resid,
    float* __restrict__ Cf, __half* __restrict__ Ch, int mode)
{
    extern __shared__ char smem[];
    uint32_t sb = smem_u32(smem);
    int tid = threadIdx.x, wid = tid >> 5, lane = tid & 31;
    int wm = wid >> 2, wn = wid & 3;
    int m0 = blockIdx.y * 128, n0 = blockIdx.x * 128;

    auto load_chunk = [&](int c) {
        int kt = c << 6;
        uint32_t st = sb + (c & 1) * STG;
        #pragma unroll
        for (int o = 0; o < 8; o++) {
            int flat = o * 256 + tid;          // 0..2047
            int op = flat >> 10, wi = flat & 1023;
            int row = wi >> 3, c16 = wi & 7;
            uint32_t dst = st + op * OPB + row * ROWB + c16 * 16;
            const __half* src;
            if (op == 0) {
                src = A + (size_t)(m0 + row) * K + kt + c16 * 8;
            } else {
                int r = n0 + row; if (r >= N) r = N - 1;
                src = Bm + (size_t)r * K + kt + c16 * 8;
            }
            asm volatile("cp.async.cg.shared.global [%0], [%1], 16;" :: "r"(dst), "l"(src));
        }
        asm volatile("cp.async.commit_group;" ::: "memory");
    };

    float acc[4][4][4] = {};
    int nc = K >> 6;

    load_chunk(0);
    load_chunk(1);

    for (int c = 0; c < nc; c++) {
        if (c + 1 < nc) asm volatile("cp.async.wait_group 1;" ::: "memory");
        else            asm volatile("cp.async.wait_group 0;" ::: "memory");
        __syncthreads();
        uint32_t st = sb + (c & 1) * STG;
        uint32_t a_row = (uint32_t)(wm * 64 + (lane & 15)) * ROWB + (lane >> 4) * 16;
        uint32_t b_row = (uint32_t)(wn * 32 + (lane & 7) + ((lane >> 4) & 1) * 8) * ROWB
                       + ((lane >> 3) & 1) * 16;
        #pragma unroll
        for (int kk = 0; kk < 4; kk++) {
            uint32_t ah[4][4], bh[4][2];
            #pragma unroll
            for (int mt = 0; mt < 4; mt++) {
                uint32_t ad = st + a_row + mt * (16 * ROWB) + kk * 32;
                ldsm4(ah[mt][0], ah[mt][1], ah[mt][2], ah[mt][3], ad);
            }
            #pragma unroll
            for (int np = 0; np < 2; np++) {
                uint32_t bd = st + OPB + b_row + np * (16 * ROWB) + kk * 32;
                ldsm4(bh[np*2][0], bh[np*2][1], bh[np*2+1][0], bh[np*2+1][1], bd);
            }
            #pragma unroll
            for (int mt = 0; mt < 4; mt++)
                #pragma unroll
                for (int nt = 0; nt < 4; nt++)
                    mma16816(acc[mt][nt], ah[mt], bh[nt]);
        }
        __syncthreads();
        if (c + 2 < nc) load_chunk(c + 2);
    }

    // epilogue
    #pragma unroll
    for (int mt = 0; mt < 4; mt++) {
        #pragma unroll
        for (int nt = 0; nt < 4; nt++) {
            int mbase = m0 + wm * 64 + mt * 16 + (lane >> 2);
            int nbase = n0 + wn * 32 + nt * 8 + (lane & 3) * 2;
            #pragma unroll
            for (int hrow = 0; hrow < 2; hrow++) {
                int m = mbase + hrow * 8;
                #pragma unroll
                for (int jj = 0; jj < 2; jj++) {
                    int n = nbase + jj;
                    float v = acc[mt][nt][hrow * 2 + jj];
                    if (mode == 2) {
                        // qkv split: n in [0,2304)
                        int sct = n / Dd, r = n - sct * Dd;
                        int h = r / HDim, hd = r - h * HDim;
                        int bb = m >> 9, t = m & (Tt - 1);
                        int bh_ = bb * Hh + h;
                        if (sct == 0)      g_q [((size_t)bh_ * Tt + t) * HDim + hd] = v;
                        else if (sct == 1) g_k [((size_t)bh_ * Tt + t) * HDim + hd] = v;
                        else               g_vt[((size_t)bh_ * HDim + hd) * Tt + t] = v;
                    } else if (n < N) {
                        if (bias) v += bias[n];
                        if (mode == 1) v = 0.5f * v * (1.0f + erff(v * 0.70710678118654752f));
                        size_t ix = (size_t)m * N + n;
                        if (resid) v += resid[ix];
                        if (Cf) Cf[ix] = v;
                        if (Ch) Ch[ix] = __float2half(v);
                    }
                }
            }
        }
    }
}

// ---------------- batched attention NT GEMM (fp32) ----------------
// mode 0: scores = Q*K^T*scale, causal mask ; mode 1: O = P*Vt^T -> fp16 [B,T,D]
__global__ __launch_bounds__(256) void attn_gemm_k(
    const float* __restrict__ A, const float* __restrict__ Bm, float* __restrict__ C,
    __half* __restrict__ Oh, int N, int K, long sA, long sB, int mode) {
    int z = blockIdx.z;
    int n0 = blockIdx.x * 128, m0 = blockIdx.y * 128;
    if (mode == 0 && n0 > m0 + 127) return;
    A += (size_t)z * sA;
    Bm += (size_t)z * sB;
    __shared__ float As[16][128];
    __shared__ float Bs[16][128];
    int tid = threadIdx.x;
    int tx = tid & 15, ty = tid >> 4;
    float acc[8][8] = {};
    for (int kt = 0; kt < K; kt += 16) {
        #pragma unroll
        for (int i = 0; i < 2; i++) {
            int f = tid * 2 + i;
            int r = f >> 2, kq = (f & 3) * 4;
            float4 va = *(const float4*)(A + (size_t)(m0 + r) * K + kt + kq);
            As[kq][r] = va.x; As[kq + 1][r] = va.y; As[kq + 2][r] = va.z; As[kq + 3][r] = va.w;
            float4 vb = make_float4(0.f, 0.f, 0.f, 0.f);
            if (n0 + r < N) vb = *(const float4*)(Bm + (size_t)(n0 + r) * K + kt + kq);
            Bs[kq][r] = vb.x; Bs[kq + 1][r] = vb.y; Bs[kq + 2][r] = vb.z; Bs[kq + 3][r] = vb.w;
        }
        __syncthreads();
        #pragma unroll
        for (int kk = 0; kk < 16; kk++) {
            float a[8], bfr[8];
            *(float4*)(a)       = *(const float4*)&As[kk][ty * 8];
            *(float4*)(a + 4)   = *(const float4*)&As[kk][ty * 8 + 4];
            *(float4*)(bfr)     = *(const float4*)&Bs[kk][tx * 8];
            *(float4*)(bfr + 4) = *(const float4*)&Bs[kk][tx * 8 + 4];
            #pragma unroll
            for (int i = 0; i < 8; i++)
                #pragma unroll
                for (int j = 0; j < 8; j++)
                    acc[i][j] += a[i] * bfr[j];
        }
        __syncthreads();
    }
    if (mode == 0) {
        float* Cb = C + (size_t)z * Tt * Tt;
        #pragma unroll
        for (int i = 0; i < 8; i++) {
            int q = m0 + ty * 8 + i;
            #pragma unroll
            for (int j = 0; j < 8; j++) {
                int k = n0 + tx * 8 + j;
                Cb[(size_t)q * Tt + k] = (k <= q) ? acc[i][j] * ATT_SCALE : -1e30f;
            }
        }
    } else {
        int bb = z / Hh, h = z - bb * Hh;
        size_t base = (size_t)bb * Tt * Dd + h * HDim;
        #pragma unroll
        for (int i = 0; i < 8; i++) {
            int m = m0 + ty * 8 + i;
            #pragma unroll
            for (int j = 0; j < 8; j++) {
                int n = n0 + tx * 8 + j;
                if (n < N) Oh[base + (size_t)m * Dd + n] = __float2half(acc[i][j]);
            }
        }
    }
}

// ---------------- causal row softmax ----------------
__global__ void softmax_k(float* __restrict__ S) {
    int bid = blockIdx.x;
    int q = bid & (Tt - 1);
    int bh = bid >> 9;
    float* row = S + ((size_t)bh * Tt + q) * Tt;
    int len = q + 1;
    int tid = threadIdx.x;
    __shared__ float red[128];
    float mx = -1e30f;
    for (int k = tid; k < len; k += 128) mx = fmaxf(mx, row[k]);
    red[tid] = mx;
    __syncthreads();
    #pragma unroll
    for (int st = 64; st > 0; st >>= 1) { if (tid < st) red[tid] = fmaxf(red[tid], red[tid + st]); __syncthreads(); }
    mx = red[0];
    __syncthreads();
    float sum = 0.f;
    for (int k = tid; k < len; k += 128) { float e = expf(row[k] - mx); row[k] = e; sum += e; }
    red[tid] = sum;
    __syncthreads();
    #pragma unroll
    for (int st = 64; st > 0; st >>= 1) { if (tid < st) red[tid] += red[tid + st]; __syncthreads(); }
    float inv = 1.0f / red[0];
    for (int k = tid; k < len; k += 128) row[k] *= inv;
    for (int k = len + tid; k < Tt; k += 128) row[k] = 0.f;
}

// ---------------- launch ----------------
extern "C" void kernel_launch(void* const* d_in, const int* in_sizes, int n_in,
                              void* d_out, int out_size) {
    const int*   idx    = (const int*)  d_in[0];
    const float* tok    = (const float*)d_in[1];
    const float* pos    = (const float*)d_in[2];
    const float* ln1_s  = (const float*)d_in[3];
    const float* ln1_b  = (const float*)d_in[4];
    const float* qkv_w  = (const float*)d_in[5];
    const float* out_w  = (const float*)d_in[6];
    const float* ln2_s  = (const float*)d_in[7];
    const float* ln2_b  = (const float*)d_in[8];
    const float* ffn_w1 = (const float*)d_in[9];
    const float* ffn_b1 = (const float*)d_in[10];
    const float* ffn_w2 = (const float*)d_in[11];
    const float* ffn_b2 = (const float*)d_in[12];
    const float* fn_s   = (const float*)d_in[13];
    const float* fn_b   = (const float*)d_in[14];
    const float* head_w = (const float*)d_in[15];

    float* logits = (float*)d_out;
    float* hidden = logits + (size_t)Bz * Tt * Vv;

    float *x, *q, *k, *vt, *s;
    __half *h16, *o16, *f16, *wq, *wo, *w1, *w2, *wh;
    cudaGetSymbolAddress((void**)&x,   g_x);
    cudaGetSymbolAddress((void**)&q,   g_q);
    cudaGetSymbolAddress((void**)&k,   g_k);
    cudaGetSymbolAddress((void**)&vt,  g_vt);
    cudaGetSymbolAddress((void**)&s,   g_s);
    cudaGetSymbolAddress((void**)&h16, g_h16);
    cudaGetSymbolAddress((void**)&o16, g_o16);
    cudaGetSymbolAddress((void**)&f16, g_f16);
    cudaGetSymbolAddress((void**)&wq,  g_wq);
    cudaGetSymbolAddress((void**)&wo,  g_wo);
    cudaGetSymbolAddress((void**)&w1,  g_w1);
    cudaGetSymbolAddress((void**)&w2,  g_w2);
    cudaGetSymbolAddress((void**)&wh,  g_wh);

    cudaFuncSetAttribute(gemm_mm, cudaFuncAttributeMaxDynamicSharedMemorySize, SMEM_MM);

    {
        size_t n1 = (size_t)Ll * 3 * Dd * Dd / 4;
        size_t n2 = (size_t)Ll * Dd * Dd / 4;
        size_t n3 = (size_t)Ll * 4 * Dd * Dd / 4;
        size_t n5 = (size_t)Vv * Dd / 4;
        cvt_k<<<(unsigned)((n1 + 255) / 256), 256>>>(qkv_w,  wq, n1);
        cvt_k<<<(unsigned)((n2 + 255) / 256), 256>>>(out_w,  wo, n2);
        cvt_k<<<(unsigned)((n3 + 255) / 256), 256>>>(ffn_w1, w1, n3);
        cvt_k<<<(unsigned)((n3 + 255) / 256), 256>>>(ffn_w2, w2, n3);
        cvt_k<<<(unsigned)((n5 + 255) / 256), 256>>>(head_w, wh, n5);
    }

    embed_k<<<(MR * Dd) / 256, 256>>>(idx, tok, pos, x);

    for (int l = 0; l < Ll; l++) {
        ln_k<<<MR, 256>>>(x, ln1_s + l * Dd, ln1_b + l * Dd, h16, nullptr);
        gemm_mm<<<dim3(18, 16), 256, SMEM_MM>>>(h16, wq + (size_t)l * 3 * Dd * Dd,
                                                3 * Dd, Dd, nullptr, nullptr, nullptr, nullptr, 2);
        attn_gemm_k<<<dim3(4, 4, Bz * Hh), 256>>>(q, k, s, nullptr, Tt, HDim,
                                                  (long)Tt * HDim, (long)Tt * HDim, 0);
        softmax_k<<<Bz * Hh * Tt, 128>>>(s);
        attn_gemm_k<<<dim3(1, 4, Bz * Hh), 256>>>(s, vt, nullptr, o16, HDim, Tt,
                                                  (long)Tt * Tt, (long)HDim * Tt, 1);
        gemm_mm<<<dim3(6, 16), 256, SMEM_MM>>>(o16, wo + (size_t)l * Dd * Dd,
                                               Dd, Dd, nullptr, x, x, nullptr, 0);
        ln_k<<<MR, 256>>>(x, ln2_s + l * Dd, ln2_b + l * Dd, h16, nullptr);
        gemm_mm<<<dim3(24, 16), 256, SMEM_MM>>>(h16, w1 + (size_t)l * 4 * Dd * Dd,
                                                4 * Dd, Dd, ffn_b1 + l * 4 * Dd, nullptr,
                                                nullptr, f16, 1);
        gemm_mm<<<dim3(6, 16), 256, SMEM_MM>>>(f16, w2 + (size_t)l * 4 * Dd * Dd,
                                               Dd, 4 * Dd, ffn_b2 + l * Dd, x, x, nullptr, 0);
    }

    ln_k<<<MR, 256>>>(x, fn_s, fn_b, h16, hidden);
    gemm_mm<<<dim3(393, 16), 256, SMEM_MM>>>(h16, wh, Vv, Dd,
                                             nullptr, nullptr, logits, nullptr, 0);
}

// round 6
// speedup vs baseline: 4.5576x; 1.1453x over previous
#include <cuda_runtime.h>
#include <cuda_fp16.h>
#include <math.h>
#include <stdint.h>

#define Bz   4
#define Tt   512
#define Dd   768
#define Hh   8
#define HDim 96
#define HDP  128            // padded head dim for MMA
#define Ll   12
#define Vv   50257
#define MR   (Bz*Tt)
#define BH   (Bz*Hh)
#define ATT_SCALE 0.10206207261596575f

__device__ __forceinline__ uint32_t smem_u32(const void* p) {
    uint32_t a;
    asm("{ .reg .u64 t; cvta.to.shared.u64 t, %1; cvt.u32.u64 %0, t; }" : "=r"(a) : "l"(p));
    return a;
}

// ---------------- scratch (device globals) ----------------
__device__ float g_x [MR*Dd];
__device__ float g_s [(size_t)BH*Tt*Tt];
__device__ __align__(16) __half g_h16[MR*Dd];
__device__ __align__(16) __half g_f16[MR*4*Dd];
__device__ __align__(16) __half g_qh[(size_t)BH*Tt*HDP], g_ql[(size_t)BH*Tt*HDP];
__device__ __align__(16) __half g_kh[(size_t)BH*Tt*HDP], g_kl[(size_t)BH*Tt*HDP];
__device__ __align__(16) __half g_vth[(size_t)BH*HDim*Tt];
__device__ __align__(16) __half g_ph[(size_t)BH*Tt*Tt], g_pl[(size_t)BH*Tt*Tt];
__device__ __align__(16) __half g_oh[MR*Dd], g_ol[MR*Dd];
__device__ __align__(16) __half g_wq[(size_t)Ll*3*Dd*Dd];
__device__ __align__(16) __half g_wo[(size_t)Ll*Dd*Dd];
__device__ __align__(16) __half g_w1[(size_t)Ll*4*Dd*Dd];
__device__ __align__(16) __half g_w2[(size_t)Ll*4*Dd*Dd];
__device__ __align__(16) __half g_wh[(size_t)Vv*Dd];

// ---------------- weight fp32 -> fp16 ----------------
__global__ void cvt_k(const float* __restrict__ w, __half* __restrict__ o, size_t n4) {
    size_t i = (size_t)blockIdx.x * 256 + threadIdx.x;
    if (i >= n4) return;
    float4 v = ((const float4*)w)[i];
    ((__half2*)o)[i * 2]     = __floats2half2_rn(v.x, v.y);
    ((__half2*)o)[i * 2 + 1] = __floats2half2_rn(v.z, v.w);
}

// ---------------- embedding ----------------
__global__ void embed_k(const int* __restrict__ idx, const float* __restrict__ tok,
                        const float* __restrict__ pos, float* __restrict__ x) {
    int i = blockIdx.x * 256 + threadIdx.x;
    int m = i / Dd, d = i - m * Dd;
    int t = m & (Tt - 1);
    x[i] = tok[(size_t)idx[m] * Dd + d] + pos[t * Dd + d];
}

// ---------------- layernorm -> fp16 (+ optional fp32) ----------------
__global__ void ln_k(const float* __restrict__ in, const float* __restrict__ s,
                     const float* __restrict__ b, __half* __restrict__ oh,
                     float* __restrict__ ofp) {
    int m = blockIdx.x, tid = threadIdx.x;
    const float* row = in + (size_t)m * Dd;
    float x0 = row[tid], x1 = row[tid + 256], x2 = row[tid + 512];
    __shared__ float red[256];
    red[tid] = x0 + x1 + x2;
    __syncthreads();
    #pragma unroll
    for (int st = 128; st > 0; st >>= 1) { if (tid < st) red[tid] += red[tid + st]; __syncthreads(); }
    float mean = red[0] * (1.0f / Dd);
    __syncthreads();
    float d0 = x0 - mean, d1 = x1 - mean, d2 = x2 - mean;
    red[tid] = d0 * d0 + d1 * d1 + d2 * d2;
    __syncthreads();
    #pragma unroll
    for (int st = 128; st > 0; st >>= 1) { if (tid < st) red[tid] += red[tid + st]; __syncthreads(); }
    float inv = rsqrtf(red[0] * (1.0f / Dd) + 1e-5f);
    size_t base = (size_t)m * Dd;
    #pragma unroll
    for (int q = 0; q < 3; q++) {
        int c = tid + q * 256;
        float dv = (q == 0 ? d0 : (q == 1 ? d1 : d2));
        float v = dv * inv * s[c] + b[c];
        oh[base + c] = __float2half(v);
        if (ofp) ofp[base + c] = v;
    }
}

// ---------------- HMMA primitives ----------------
__device__ __forceinline__ void ldsm4(uint32_t& r0, uint32_t& r1, uint32_t& r2, uint32_t& r3,
                                      uint32_t addr) {
    asm volatile("ldmatrix.sync.aligned.m8n8.x4.shared.b16 {%0,%1,%2,%3}, [%4];"
                 : "=r"(r0), "=r"(r1), "=r"(r2), "=r"(r3) : "r"(addr));
}
__device__ __forceinline__ void mma16816(float* d, const uint32_t* a, const uint32_t* b) {
    asm volatile("mma.sync.aligned.m16n8k16.row.col.f32.f16.f16.f32 "
                 "{%0,%1,%2,%3}, {%4,%5,%6,%7}, {%8,%9}, {%0,%1,%2,%3};"
                 : "+f"(d[0]), "+f"(d[1]), "+f"(d[2]), "+f"(d[3])
                 : "r"(a[0]), "r"(a[1]), "r"(a[2]), "r"(a[3]), "r"(b[0]), "r"(b[1]));
}

#define ROWB 144
#define OPB  (128*ROWB)
#define STG  (2*OPB)
#define SMEM_MM (2*STG)        // 73728 (2 operands, 2 stages)
#define STG4 (4*OPB)
#define SMEM_AT (2*STG4)       // 147456 (4 operands, 2 stages)

// ---------------- main fp16 GEMM: C[M,N] = A[M,K]*B[N,K]^T, fp32 acc ----------
// mode: 0 normal | 1 gelu(bias) | 2 qkv split scatter (fp16 hi/lo q,k + v^T)
__global__ __launch_bounds__(256, 2) void gemm_mm(
    const __half* __restrict__ A, const __half* __restrict__ Bm,
    int N, int K,
    const float* __restrict__ bias, const float* __restrict__ resid,
    float* __restrict__ Cf, __half* __restrict__ Ch, int mode)
{
    extern __shared__ char smem[];
    uint32_t sb = smem_u32(smem);
    int tid = threadIdx.x, wid = tid >> 5, lane = tid & 31;
    int wm = wid >> 2, wn = wid & 3;
    int m0 = blockIdx.y * 128, n0 = blockIdx.x * 128;

    auto load_chunk = [&](int c) {
        int kt = c << 6;
        uint32_t st = sb + (c & 1) * STG;
        #pragma unroll
        for (int o = 0; o < 8; o++) {
            int flat = o * 256 + tid;
            int op = flat >> 10, wi = flat & 1023;
            int row = wi >> 3, c16 = wi & 7;
            uint32_t dst = st + op * OPB + row * ROWB + c16 * 16;
            const __half* src;
            if (op == 0) {
                src = A + (size_t)(m0 + row) * K + kt + c16 * 8;
            } else {
                int r = n0 + row; if (r >= N) r = N - 1;
                src = Bm + (size_t)r * K + kt + c16 * 8;
            }
            asm volatile("cp.async.cg.shared.global [%0], [%1], 16;" :: "r"(dst), "l"(src));
        }
        asm volatile("cp.async.commit_group;" ::: "memory");
    };

    float acc[4][4][4] = {};
    int nc = K >> 6;

    load_chunk(0);
    load_chunk(1);

    for (int c = 0; c < nc; c++) {
        if (c + 1 < nc) asm volatile("cp.async.wait_group 1;" ::: "memory");
        else            asm volatile("cp.async.wait_group 0;" ::: "memory");
        __syncthreads();
        uint32_t st = sb + (c & 1) * STG;
        uint32_t a_row = (uint32_t)(wm * 64 + (lane & 15)) * ROWB + (lane >> 4) * 16;
        uint32_t b_row = (uint32_t)(wn * 32 + (lane & 7) + ((lane >> 4) & 1) * 8) * ROWB
                       + ((lane >> 3) & 1) * 16;
        #pragma unroll
        for (int kk = 0; kk < 4; kk++) {
            uint32_t ah[4][4], bh[4][2];
            #pragma unroll
            for (int mt = 0; mt < 4; mt++) {
                uint32_t ad = st + a_row + mt * (16 * ROWB) + kk * 32;
                ldsm4(ah[mt][0], ah[mt][1], ah[mt][2], ah[mt][3], ad);
            }
            #pragma unroll
            for (int np = 0; np < 2; np++) {
                uint32_t bd = st + OPB + b_row + np * (16 * ROWB) + kk * 32;
                ldsm4(bh[np*2][0], bh[np*2][1], bh[np*2+1][0], bh[np*2+1][1], bd);
            }
            #pragma unroll
            for (int mt = 0; mt < 4; mt++)
                #pragma unroll
                for (int nt = 0; nt < 4; nt++)
                    mma16816(acc[mt][nt], ah[mt], bh[nt]);
        }
        __syncthreads();
        if (c + 2 < nc) load_chunk(c + 2);
    }

    #pragma unroll
    for (int mt = 0; mt < 4; mt++) {
        #pragma unroll
        for (int nt = 0; nt < 4; nt++) {
            int mbase = m0 + wm * 64 + mt * 16 + (lane >> 2);
            int nbase = n0 + wn * 32 + nt * 8 + (lane & 3) * 2;
            #pragma unroll
            for (int hrow = 0; hrow < 2; hrow++) {
                int m = mbase + hrow * 8;
                #pragma unroll
                for (int jj = 0; jj < 2; jj++) {
                    int n = nbase + jj;
                    float v = acc[mt][nt][hrow * 2 + jj];
                    if (mode == 2) {
                        int sct = n / Dd, r = n - sct * Dd;
                        int h = r / HDim, hd = r - h * HDim;
                        int bb = m >> 9, t = m & (Tt - 1);
                        int bh_ = bb * Hh + h;
                        if (sct == 0) {
                            size_t ix = ((size_t)bh_ * Tt + t) * HDP + hd;
                            __half hv = __float2half(v);
                            g_qh[ix] = hv;
                            g_ql[ix] = __float2half(v - __half2float(hv));
                        } else if (sct == 1) {
                            size_t ix = ((size_t)bh_ * Tt + t) * HDP + hd;
                            __half hv = __float2half(v);
                            g_kh[ix] = hv;
                            g_kl[ix] = __float2half(v - __half2float(hv));
                        } else {
                            g_vth[((size_t)bh_ * HDim + hd) * Tt + t] = __float2half(v);
                        }
                    } else if (n < N) {
                        if (bias) v += bias[n];
                        if (mode == 1) v = 0.5f * v * (1.0f + erff(v * 0.70710678118654752f));
                        size_t ix = (size_t)m * N + n;
                        if (resid) v += resid[ix];
                        if (Cf) Cf[ix] = v;
                        if (Ch) Ch[ix] = __float2half(v);
                    }
                }
            }
        }
    }
}

// ---------------- attention MMA (split-precision) ----------------
// mode 0: S = (Ah+Al)*(Bh+Bl)^T * scale, causal mask   (3 passes, 4 operands)
// mode 1: O = (Ah+Al)*Bh^T -> oh/ol fp16 in [B,T,D]    (2 passes, 3 operands)
__global__ __launch_bounds__(256, 1) void attn_mma(
    const __half* __restrict__ Ah, const __half* __restrict__ Al,
    const __half* __restrict__ Bh, const __half* __restrict__ Bl,
    float* __restrict__ S, __half* __restrict__ Oh, __half* __restrict__ Ol,
    int K, int Nb, long sA, long sB, int mode)
{
    int z = blockIdx.z;
    int n0 = blockIdx.x * 128, m0 = blockIdx.y * 128;
    if (mode == 0 && n0 > m0 + 127) return;   // above causal diagonal (softmax never reads there)

    extern __shared__ char smem[];
    uint32_t sb = smem_u32(smem);
    int tid = threadIdx.x, wid = tid >> 5, lane = tid & 31;
    int wm = wid >> 2, wn = wid & 3;

    const __half* opp[4];
    opp[0] = Ah + (size_t)z * sA;
    opp[1] = Al + (size_t)z * sA;
    opp[2] = Bh + (size_t)z * sB;
    opp[3] = (mode == 0) ? (Bl + (size_t)z * sB) : opp[2];
    int nops = (mode == 0) ? 4 : 3;

    auto load_chunk = [&](int c) {
        int kt = c << 6;
        uint32_t st = sb + (c & 1) * STG4;
        for (int o = 0; o < nops * 4; o++) {
            int flat = o * 256 + tid;
            int op = flat >> 10, wi = flat & 1023;
            int row = wi >> 3, c16 = wi & 7;
            uint32_t dst = st + op * OPB + row * ROWB + c16 * 16;
            int r;
            if (op >= 2) { r = n0 + row; if (r >= Nb) r = Nb - 1; }
            else         { r = m0 + row; }
            const __half* src = opp[op] + (size_t)r * K + kt + c16 * 8;
            asm volatile("cp.async.cg.shared.global [%0], [%1], 16;" :: "r"(dst), "l"(src));
        }
        asm volatile("cp.async.commit_group;" ::: "memory");
    };

    float acc[4][4][4] = {};
    int nc = K >> 6;

    load_chunk(0);
    load_chunk(1);

    for (int c = 0; c < nc; c++) {
        if (c + 1 < nc) asm volatile("cp.async.wait_group 1;" ::: "memory");
        else            asm volatile("cp.async.wait_group 0;" ::: "memory");
        __syncthreads();
        uint32_t st = sb + (c & 1) * STG4;
        uint32_t a_row = (uint32_t)(wm * 64 + (lane & 15)) * ROWB + (lane >> 4) * 16;
        uint32_t b_row = (uint32_t)(wn * 32 + (lane & 7) + ((lane >> 4) & 1) * 8) * ROWB
                       + ((lane >> 3) & 1) * 16;
        #pragma unroll
        for (int kk = 0; kk < 4; kk++) {
            uint32_t ah[4][4], al[4][4], bh2[4][2], bl2[4][2];
            #pragma unroll
            for (int mt = 0; mt < 4; mt++) {
                uint32_t ad = st + a_row + mt * (16 * ROWB) + kk * 32;
                ldsm4(ah[mt][0], ah[mt][1], ah[mt][2], ah[mt][3], ad);
                ldsm4(al[mt][0], al[mt][1], al[mt][2], al[mt][3], ad + OPB);
            }
            #pragma unroll
            for (int np = 0; np < 2; np++) {
                uint32_t bd = st + 2 * OPB + b_row + np * (16 * ROWB) + kk * 32;
                ldsm4(bh2[np*2][0], bh2[np*2][1], bh2[np*2+1][0], bh2[np*2+1][1], bd);
            }
            if (mode == 0) {
                #pragma unroll
                for (int np = 0; np < 2; np++) {
                    uint32_t bd = st + 3 * OPB + b_row + np * (16 * ROWB) + kk * 32;
                    ldsm4(bl2[np*2][0], bl2[np*2][1], bl2[np*2+1][0], bl2[np*2+1][1], bd);
                }
            }
            #pragma unroll
            for (int mt = 0; mt < 4; mt++)
                #pragma unroll
                for (int nt = 0; nt < 4; nt++)
                    mma16816(acc[mt][nt], ah[mt], bh2[nt]);
            #pragma unroll
            for (int mt = 0; mt < 4; mt++)
                #pragma unroll
                for (int nt = 0; nt < 4; nt++)
                    mma16816(acc[mt][nt], al[mt], bh2[nt]);
            if (mode == 0) {
                #pragma unroll
                for (int mt = 0; mt < 4; mt++)
                    #pragma unroll
                    for (int nt = 0; nt < 4; nt++)
                        mma16816(acc[mt][nt], ah[mt], bl2[nt]);
            }
        }
        __syncthreads();
        if (c + 2 < nc) load_chunk(c + 2);
    }

    if (mode == 0) {
        float* Cb = S + (size_t)z * Tt * Tt;
        #pragma unroll
        for (int mt = 0; mt < 4; mt++) {
            #pragma unroll
            for (int nt = 0; nt < 4; nt++) {
                int mbase = m0 + wm * 64 + mt * 16 + (lane >> 2);
                int nbase = n0 + wn * 32 + nt * 8 + (lane & 3) * 2;
                #pragma unroll
                for (int hrow = 0; hrow < 2; hrow++) {
                    int q = mbase + hrow * 8;
                    #pragma unroll
                    for (int jj = 0; jj < 2; jj++) {
                        int kcol = nbase + jj;
                        Cb[(size_t)q * Tt + kcol] =
                            (kcol <= q) ? acc[mt][nt][hrow * 2 + jj] * ATT_SCALE : -1e30f;
                    }
                }
            }
        }
    } else {
        int bb = z >> 3, h = z & 7;
        size_t base = (size_t)bb * Tt * Dd + (size_t)h * HDim;
        #pragma unroll
        for (int mt = 0; mt < 4; mt++) {
            #pragma unroll
            for (int nt = 0; nt < 4; nt++) {
                int mbase = m0 + wm * 64 + mt * 16 + (lane >> 2);
                int nbase = n0 + wn * 32 + nt * 8 + (lane & 3) * 2;
                #pragma unroll
                for (int hrow = 0; hrow < 2; hrow++) {
                    int t = mbase + hrow * 8;
                    #pragma unroll
                    for (int jj = 0; jj < 2; jj++) {
                        int n = nbase + jj;
                        if (n < Nb) {
                            float v = acc[mt][nt][hrow * 2 + jj];
                            size_t ix = base + (size_t)t * Dd + n;
                            __half hv = __float2half(v);
                            g_oh[ix] = hv;
                            g_ol[ix] = __float2half(v - __half2float(hv));
                        }
                    }
                }
            }
        }
    }
}

// ---------------- causal softmax: S fp32 (k<=q only) -> p fp16 hi/lo, zero tail --
__global__ void softmax_k(const float* __restrict__ S, __half* __restrict__ ph,
                          __half* __restrict__ pl) {
    int bid = blockIdx.x;
    int q = bid & (Tt - 1);
    int bh = bid >> 9;
    const float* row = S + ((size_t)bh * Tt + q) * Tt;
    int len = q + 1;
    int tid = threadIdx.x;   // 128
    float v[4];
    float mx = -1e30f;
    #pragma unroll
    for (int j = 0; j < 4; j++) {
        int kcol = j * 128 + tid;
        v[j] = (kcol < len) ? row[kcol] : -1e30f;   // never read above causal diagonal
        mx = fmaxf(mx, v[j]);
    }
    __shared__ float red[128];
    red[tid] = mx;
    __syncthreads();
    #pragma unroll
    for (int st = 64; st > 0; st >>= 1) { if (tid < st) red[tid] = fmaxf(red[tid], red[tid + st]); __syncthreads(); }
    mx = red[0];
    __syncthreads();
    float sum = 0.f;
    #pragma unroll
    for (int j = 0; j < 4; j++) {
        int kcol = j * 128 + tid;
        v[j] = (kcol < len) ? expf(v[j] - mx) : 0.f;
        sum += v[j];
    }
    red[tid] = sum;
    __syncthreads();
    #pragma unroll
    for (int st = 64; st > 0; st >>= 1) { if (tid < st) red[tid] += red[tid + st]; __syncthreads(); }
    float inv = 1.0f / red[0];
    size_t base = ((size_t)bh * Tt + q) * Tt;
    #pragma unroll
    for (int j = 0; j < 4; j++) {
        float p = v[j] * inv;                        // 0 in masked tail
        __half hp = __float2half(p);
        size_t ix = base + j * 128 + tid;
        ph[ix] = hp;
        pl[ix] = __float2half(p - __half2float(hp));
    }
}

// ---------------- launch ----------------
extern "C" void kernel_launch(void* const* d_in, const int* in_sizes, int n_in,
                              void* d_out, int out_size) {
    const int*   idx    = (const int*)  d_in[0];
    const float* tok    = (const float*)d_in[1];
    const float* pos    = (const float*)d_in[2];
    const float* ln1_s  = (const float*)d_in[3];
    const float* ln1_b  = (const float*)d_in[4];
    const float* qkv_w  = (const float*)d_in[5];
    const float* out_w  = (const float*)d_in[6];
    const float* ln2_s  = (const float*)d_in[7];
    const float* ln2_b  = (const float*)d_in[8];
    const float* ffn_w1 = (const float*)d_in[9];
    const float* ffn_b1 = (const float*)d_in[10];
    const float* ffn_w2 = (const float*)d_in[11];
    const float* ffn_b2 = (const float*)d_in[12];
    const float* fn_s   = (const float*)d_in[13];
    const float* fn_b   = (const float*)d_in[14];
    const float* head_w = (const float*)d_in[15];

    float* logits = (float*)d_out;
    float* hidden = logits + (size_t)Bz * Tt * Vv;

    float *x, *s;
    __half *h16, *f16, *qh, *ql, *kh, *kl, *vth, *ph, *pl, *oh, *ol;
    __half *wq, *wo, *w1, *w2, *wh;
    cudaGetSymbolAddress((void**)&x,   g_x);
    cudaGetSymbolAddress((void**)&s,   g_s);
    cudaGetSymbolAddress((void**)&h16, g_h16);
    cudaGetSymbolAddress((void**)&f16, g_f16);
    cudaGetSymbolAddress((void**)&qh,  g_qh);  cudaGetSymbolAddress((void**)&ql, g_ql);
    cudaGetSymbolAddress((void**)&kh,  g_kh);  cudaGetSymbolAddress((void**)&kl, g_kl);
    cudaGetSymbolAddress((void**)&vth, g_vth);
    cudaGetSymbolAddress((void**)&ph,  g_ph);  cudaGetSymbolAddress((void**)&pl, g_pl);
    cudaGetSymbolAddress((void**)&oh,  g_oh);  cudaGetSymbolAddress((void**)&ol, g_ol);
    cudaGetSymbolAddress((void**)&wq,  g_wq);
    cudaGetSymbolAddress((void**)&wo,  g_wo);
    cudaGetSymbolAddress((void**)&w1,  g_w1);
    cudaGetSymbolAddress((void**)&w2,  g_w2);
    cudaGetSymbolAddress((void**)&wh,  g_wh);

    cudaFuncSetAttribute(gemm_mm,  cudaFuncAttributeMaxDynamicSharedMemorySize, SMEM_MM);
    cudaFuncSetAttribute(attn_mma, cudaFuncAttributeMaxDynamicSharedMemorySize, SMEM_AT);

    {
        size_t n1 = (size_t)Ll * 3 * Dd * Dd / 4;
        size_t n2 = (size_t)Ll * Dd * Dd / 4;
        size_t n3 = (size_t)Ll * 4 * Dd * Dd / 4;
        size_t n5 = (size_t)Vv * Dd / 4;
        cvt_k<<<(unsigned)((n1 + 255) / 256), 256>>>(qkv_w,  wq, n1);
        cvt_k<<<(unsigned)((n2 + 255) / 256), 256>>>(out_w,  wo, n2);
        cvt_k<<<(unsigned)((n3 + 255) / 256), 256>>>(ffn_w1, w1, n3);
        cvt_k<<<(unsigned)((n3 + 255) / 256), 256>>>(ffn_w2, w2, n3);
        cvt_k<<<(unsigned)((n5 + 255) / 256), 256>>>(head_w, wh, n5);
    }

    embed_k<<<(MR * Dd) / 256, 256>>>(idx, tok, pos, x);

    for (int l = 0; l < Ll; l++) {
        ln_k<<<MR, 256>>>(x, ln1_s + l * Dd, ln1_b + l * Dd, h16, nullptr);
        gemm_mm<<<dim3(18, 16), 256, SMEM_MM>>>(h16, wq + (size_t)l * 3 * Dd * Dd,
                                                3 * Dd, Dd, nullptr, nullptr, nullptr, nullptr, 2);
        attn_mma<<<dim3(4, 4, BH), 256, SMEM_AT>>>(qh, ql, kh, kl, s, nullptr, nullptr,
                                                   HDP, Tt, (long)Tt * HDP, (long)Tt * HDP, 0);
        softmax_k<<<BH * Tt, 128>>>(s, ph, pl);
        attn_mma<<<dim3(1, 4, BH), 256, SMEM_AT>>>(ph, pl, vth, nullptr, nullptr, oh, ol,
                                                   Tt, HDim, (long)Tt * Tt, (long)HDim * Tt, 1);
        gemm_mm<<<dim3(6, 16), 256, SMEM_MM>>>(oh, wo + (size_t)l * Dd * Dd,
                                               Dd, Dd, nullptr, x, x, nullptr, 0);
        gemm_mm<<<dim3(6, 16), 256, SMEM_MM>>>(ol, wo + (size_t)l * Dd * Dd,
                                               Dd, Dd, nullptr, x, x, nullptr, 0);
        ln_k<<<MR, 256>>>(x, ln2_s + l * Dd, ln2_b + l * Dd, h16, nullptr);
        gemm_mm<<<dim3(24, 16), 256, SMEM_MM>>>(h16, w1 + (size_t)l * 4 * Dd * Dd,
                                                4 * Dd, Dd, ffn_b1 + l * 4 * Dd, nullptr,
                                                nullptr, f16, 1);
        gemm_mm<<<dim3(6, 16), 256, SMEM_MM>>>(f16, w2 + (size_t)l * 4 * Dd * Dd,
                                               Dd, 4 * Dd, ffn_b2 + l * Dd, x, x, nullptr, 0);
    }

    ln_k<<<MR, 256>>>(x, fn_s, fn_b, h16, hidden);
    gemm_mm<<<dim3(393, 16), 256, SMEM_MM>>>(h16, wh, Vv, Dd,
                                             nullptr, nullptr, logits, nullptr, 0);
}

// round 7
// speedup vs baseline: 4.9455x; 1.0851x over previous
#include <cuda_runtime.h>
#include <cuda_fp16.h>
#include <math.h>
#include <stdint.h>

#define Bz   4
#define Tt   512
#define Dd   768
#define Hh   8
#define HDim 96
#define HDP  128            // padded head dim for MMA
#define Ll   12
#define Vv   50257
#define MR   (Bz*Tt)
#define BH   (Bz*Hh)
#define ATT_SCALE 0.10206207261596575f

__device__ __forceinline__ uint32_t smem_u32(const void* p) {
    uint32_t a;
    asm("{ .reg .u64 t; cvta.to.shared.u64 t, %1; cvt.u32.u64 %0, t; }" : "=r"(a) : "l"(p));
    return a;
}

// ---------------- scratch (device globals) ----------------
__device__ float g_x [MR*Dd];
__device__ float g_s [(size_t)BH*Tt*Tt];
__device__ __align__(16) __half g_h16[MR*Dd];
__device__ __align__(16) __half g_f16[MR*4*Dd];
__device__ __align__(16) __half g_qh[(size_t)BH*Tt*HDP], g_ql[(size_t)BH*Tt*HDP];
__device__ __align__(16) __half g_kh[(size_t)BH*Tt*HDP], g_kl[(size_t)BH*Tt*HDP];
__device__ __align__(16) __half g_vth[(size_t)BH*HDim*Tt];
__device__ __align__(16) __half g_ph[(size_t)BH*Tt*Tt], g_pl[(size_t)BH*Tt*Tt];
__device__ __align__(16) __half g_oh[MR*Dd];
__device__ __align__(16) __half g_wq[(size_t)Ll*3*Dd*Dd];
__device__ __align__(16) __half g_wo[(size_t)Ll*Dd*Dd];
__device__ __align__(16) __half g_w1[(size_t)Ll*4*Dd*Dd];
__device__ __align__(16) __half g_w2[(size_t)Ll*4*Dd*Dd];
__device__ __align__(16) __half g_wh[(size_t)Vv*Dd];

// ---------------- weight fp32 -> fp16 ----------------
__global__ void cvt_k(const float* __restrict__ w, __half* __restrict__ o, size_t n4) {
    size_t i = (size_t)blockIdx.x * 256 + threadIdx.x;
    if (i >= n4) return;
    float4 v = ((const float4*)w)[i];
    ((__half2*)o)[i * 2]     = __floats2half2_rn(v.x, v.y);
    ((__half2*)o)[i * 2 + 1] = __floats2half2_rn(v.z, v.w);
}

// ---------------- embedding ----------------
__global__ void embed_k(const int* __restrict__ idx, const float* __restrict__ tok,
                        const float* __restrict__ pos, float* __restrict__ x) {
    int i = blockIdx.x * 256 + threadIdx.x;
    int m = i / Dd, d = i - m * Dd;
    int t = m & (Tt - 1);
    x[i] = tok[(size_t)idx[m] * Dd + d] + pos[t * Dd + d];
}

// ---------------- layernorm -> fp16 (+ optional fp32) ----------------
__global__ void ln_k(const float* __restrict__ in, const float* __restrict__ s,
                     const float* __restrict__ b, __half* __restrict__ oh,
                     float* __restrict__ ofp) {
    int m = blockIdx.x, tid = threadIdx.x;
    const float* row = in + (size_t)m * Dd;
    float x0 = row[tid], x1 = row[tid + 256], x2 = row[tid + 512];
    __shared__ float red[256];
    red[tid] = x0 + x1 + x2;
    __syncthreads();
    #pragma unroll
    for (int st = 128; st > 0; st >>= 1) { if (tid < st) red[tid] += red[tid + st]; __syncthreads(); }
    float mean = red[0] * (1.0f / Dd);
    __syncthreads();
    float d0 = x0 - mean, d1 = x1 - mean, d2 = x2 - mean;
    red[tid] = d0 * d0 + d1 * d1 + d2 * d2;
    __syncthreads();
    #pragma unroll
    for (int st = 128; st > 0; st >>= 1) { if (tid < st) red[tid] += red[tid + st]; __syncthreads(); }
    float inv = rsqrtf(red[0] * (1.0f / Dd) + 1e-5f);
    size_t base = (size_t)m * Dd;
    #pragma unroll
    for (int q = 0; q < 3; q++) {
        int c = tid + q * 256;
        float dv = (q == 0 ? d0 : (q == 1 ? d1 : d2));
        float v = dv * inv * s[c] + b[c];
        oh[base + c] = __float2half(v);
        if (ofp) ofp[base + c] = v;
    }
}

// ---------------- HMMA primitives ----------------
__device__ __forceinline__ void ldsm4(uint32_t& r0, uint32_t& r1, uint32_t& r2, uint32_t& r3,
                                      uint32_t addr) {
    asm volatile("ldmatrix.sync.aligned.m8n8.x4.shared.b16 {%0,%1,%2,%3}, [%4];"
                 : "=r"(r0), "=r"(r1), "=r"(r2), "=r"(r3) : "r"(addr));
}
__device__ __forceinline__ void mma16816(float* d, const uint32_t* a, const uint32_t* b) {
    asm volatile("mma.sync.aligned.m16n8k16.row.col.f32.f16.f16.f32 "
                 "{%0,%1,%2,%3}, {%4,%5,%6,%7}, {%8,%9}, {%0,%1,%2,%3};"
                 : "+f"(d[0]), "+f"(d[1]), "+f"(d[2]), "+f"(d[3])
                 : "r"(a[0]), "r"(a[1]), "r"(a[2]), "r"(a[3]), "r"(b[0]), "r"(b[1]));
}

#define ROWB 144
#define OPB  (128*ROWB)
#define STG  (2*OPB)
#define SMEM_MM (2*STG)        // 73728 (2 operands, 2 stages)
#define STG4 (4*OPB)
#define SMEM_AT (2*STG4)       // 147456 (4 operands, 2 stages)

// ---------------- main fp16 GEMM: C[M,N] = A[M,K]*B[N,K]^T, fp32 acc ----------
// mode: 0 normal | 1 gelu(bias) | 2 qkv split scatter (fp16 hi/lo q,k + v^T)
// swapxy: m0 from blockIdx.x (fast), n0 from blockIdx.y (slow) -> concurrent CTAs
//         share B tiles (weight streamed once; critical for the 77MB head GEMM)
__global__ __launch_bounds__(256, 2) void gemm_mm(
    const __half* __restrict__ A, const __half* __restrict__ Bm,
    int N, int K,
    const float* __restrict__ bias, const float* __restrict__ resid,
    float* __restrict__ Cf, __half* __restrict__ Ch, int mode, int swapxy)
{
    extern __shared__ char smem[];
    uint32_t sb = smem_u32(smem);
    int tid = threadIdx.x, wid = tid >> 5, lane = tid & 31;
    int wm = wid >> 2, wn = wid & 3;
    int m0 = (swapxy ? blockIdx.x : blockIdx.y) * 128;
    int n0 = (swapxy ? blockIdx.y : blockIdx.x) * 128;

    auto load_chunk = [&](int c) {
        int kt = c << 6;
        uint32_t st = sb + (c & 1) * STG;
        #pragma unroll
        for (int o = 0; o < 8; o++) {
            int flat = o * 256 + tid;
            int op = flat >> 10, wi = flat & 1023;
            int row = wi >> 3, c16 = wi & 7;
            uint32_t dst = st + op * OPB + row * ROWB + c16 * 16;
            const __half* src;
            if (op == 0) {
                src = A + (size_t)(m0 + row) * K + kt + c16 * 8;
            } else {
                int r = n0 + row; if (r >= N) r = N - 1;
                src = Bm + (size_t)r * K + kt + c16 * 8;
            }
            asm volatile("cp.async.cg.shared.global [%0], [%1], 16;" :: "r"(dst), "l"(src));
        }
        asm volatile("cp.async.commit_group;" ::: "memory");
    };

    float acc[4][4][4] = {};
    int nc = K >> 6;

    load_chunk(0);
    load_chunk(1);

    for (int c = 0; c < nc; c++) {
        if (c + 1 < nc) asm volatile("cp.async.wait_group 1;" ::: "memory");
        else            asm volatile("cp.async.wait_group 0;" ::: "memory");
        __syncthreads();
        uint32_t st = sb + (c & 1) * STG;
        uint32_t a_row = (uint32_t)(wm * 64 + (lane & 15)) * ROWB + (lane >> 4) * 16;
        uint32_t b_row = (uint32_t)(wn * 32 + (lane & 7) + ((lane >> 4) & 1) * 8) * ROWB
                       + ((lane >> 3) & 1) * 16;
        #pragma unroll
        for (int kk = 0; kk < 4; kk++) {
            uint32_t ah[4][4], bh[4][2];
            #pragma unroll
            for (int mt = 0; mt < 4; mt++) {
                uint32_t ad = st + a_row + mt * (16 * ROWB) + kk * 32;
                ldsm4(ah[mt][0], ah[mt][1], ah[mt][2], ah[mt][3], ad);
            }
            #pragma unroll
            for (int np = 0; np < 2; np++) {
                uint32_t bd = st + OPB + b_row + np * (16 * ROWB) + kk * 32;
                ldsm4(bh[np*2][0], bh[np*2][1], bh[np*2+1][0], bh[np*2+1][1], bd);
            }
            #pragma unroll
            for (int mt = 0; mt < 4; mt++)
                #pragma unroll
                for (int nt = 0; nt < 4; nt++)
                    mma16816(acc[mt][nt], ah[mt], bh[nt]);
        }
        __syncthreads();
        if (c + 2 < nc) load_chunk(c + 2);
    }

    #pragma unroll
    for (int mt = 0; mt < 4; mt++) {
        #pragma unroll
        for (int nt = 0; nt < 4; nt++) {
            int mbase = m0 + wm * 64 + mt * 16 + (lane >> 2);
            int nbase = n0 + wn * 32 + nt * 8 + (lane & 3) * 2;
            #pragma unroll
            for (int hrow = 0; hrow < 2; hrow++) {
                int m = mbase + hrow * 8;
                #pragma unroll
                for (int jj = 0; jj < 2; jj++) {
                    int n = nbase + jj;
                    float v = acc[mt][nt][hrow * 2 + jj];
                    if (mode == 2) {
                        int sct = n / Dd, r = n - sct * Dd;
                        int h = r / HDim, hd = r - h * HDim;
                        int bb = m >> 9, t = m & (Tt - 1);
                        int bh_ = bb * Hh + h;
                        if (sct == 0) {
                            size_t ix = ((size_t)bh_ * Tt + t) * HDP + hd;
                            __half hv = __float2half(v);
                            g_qh[ix] = hv;
                            g_ql[ix] = __float2half(v - __half2float(hv));
                        } else if (sct == 1) {
                            size_t ix = ((size_t)bh_ * Tt + t) * HDP + hd;
                            __half hv = __float2half(v);
                            g_kh[ix] = hv;
                            g_kl[ix] = __float2half(v - __half2float(hv));
                        } else {
                            g_vth[((size_t)bh_ * HDim + hd) * Tt + t] = __float2half(v);
                        }
                    } else if (n < N) {
                        if (bias) v += bias[n];
                        if (mode == 1) v = 0.5f * v * (1.0f + erff(v * 0.70710678118654752f));
                        size_t ix = (size_t)m * N + n;
                        if (resid) v += resid[ix];
                        if (Cf) Cf[ix] = v;
                        if (Ch) Ch[ix] = __float2half(v);
                    }
                }
            }
        }
    }
}

// ---------------- attention MMA (split-precision) ----------------
// mode 0: S = (Ah+Al)*(Bh+Bl)^T * scale, causal mask   (3 passes, 4 operands)
// mode 1: O = (Ah+Al)*Bh^T -> oh fp16 in [B,T,D]       (2 passes, 3 operands,
//         K truncated to causal extent of this m-tile)
__global__ __launch_bounds__(256, 1) void attn_mma(
    const __half* __restrict__ Ah, const __half* __restrict__ Al,
    const __half* __restrict__ Bh, const __half* __restrict__ Bl,
    float* __restrict__ S, __half* __restrict__ Oh,
    int K, int Nb, long sA, long sB, int mode)
{
    int z = blockIdx.z;
    int n0 = blockIdx.x * 128, m0 = blockIdx.y * 128;
    if (mode == 0 && n0 > m0 + 127) return;   // above causal diagonal (softmax never reads there)

    extern __shared__ char smem[];
    uint32_t sb = smem_u32(smem);
    int tid = threadIdx.x, wid = tid >> 5, lane = tid & 31;
    int wm = wid >> 2, wn = wid & 3;

    const __half* opp[4];
    opp[0] = Ah + (size_t)z * sA;
    opp[1] = Al + (size_t)z * sA;
    opp[2] = Bh + (size_t)z * sB;
    opp[3] = (mode == 0) ? (Bl + (size_t)z * sB) : opp[2];
    int nops = (mode == 0) ? 4 : 3;

    auto load_chunk = [&](int c) {
        int kt = c << 6;
        uint32_t st = sb + (c & 1) * STG4;
        for (int o = 0; o < nops * 4; o++) {
            int flat = o * 256 + tid;
            int op = flat >> 10, wi = flat & 1023;
            int row = wi >> 3, c16 = wi & 7;
            uint32_t dst = st + op * OPB + row * ROWB + c16 * 16;
            int r;
            if (op >= 2) { r = n0 + row; if (r >= Nb) r = Nb - 1; }
            else         { r = m0 + row; }
            const __half* src = opp[op] + (size_t)r * K + kt + c16 * 8;
            asm volatile("cp.async.cg.shared.global [%0], [%1], 16;" :: "r"(dst), "l"(src));
        }
        asm volatile("cp.async.commit_group;" ::: "memory");
    };

    float acc[4][4][4] = {};
    // mode 1: rows m <= m0+127 only attend to k <= m0+127 -> truncate K loop
    int nc = (mode == 1) ? ((m0 + 128) >> 6) : (K >> 6);

    load_chunk(0);
    load_chunk(1);

    for (int c = 0; c < nc; c++) {
        if (c + 1 < nc) asm volatile("cp.async.wait_group 1;" ::: "memory");
        else            asm volatile("cp.async.wait_group 0;" ::: "memory");
        __syncthreads();
        uint32_t st = sb + (c & 1) * STG4;
        uint32_t a_row = (uint32_t)(wm * 64 + (lane & 15)) * ROWB + (lane >> 4) * 16;
        uint32_t b_row = (uint32_t)(wn * 32 + (lane & 7) + ((lane >> 4) & 1) * 8) * ROWB
                       + ((lane >> 3) & 1) * 16;
        #pragma unroll
        for (int kk = 0; kk < 4; kk++) {
            uint32_t ah[4][4], al[4][4], bh2[4][2], bl2[4][2];
            #pragma unroll
            for (int mt = 0; mt < 4; mt++) {
                uint32_t ad = st + a_row + mt * (16 * ROWB) + kk * 32;
                ldsm4(ah[mt][0], ah[mt][1], ah[mt][2], ah[mt][3], ad);
                ldsm4(al[mt][0], al[mt][1], al[mt][2], al[mt][3], ad + OPB);
            }
            #pragma unroll
            for (int np = 0; np < 2; np++) {
                uint32_t bd = st + 2 * OPB + b_row + np * (16 * ROWB) + kk * 32;
                ldsm4(bh2[np*2][0], bh2[np*2][1], bh2[np*2+1][0], bh2[np*2+1][1], bd);
            }
            if (mode == 0) {
                #pragma unroll
                for (int np = 0; np < 2; np++) {
                    uint32_t bd = st + 3 * OPB + b_row + np * (16 * ROWB) + kk * 32;
                    ldsm4(bl2[np*2][0], bl2[np*2][1], bl2[np*2+1][0], bl2[np*2+1][1], bd);
                }
            }
            #pragma unroll
            for (int mt = 0; mt < 4; mt++)
                #pragma unroll
                for (int nt = 0; nt < 4; nt++)
                    mma16816(acc[mt][nt], ah[mt], bh2[nt]);
            #pragma unroll
            for (int mt = 0; mt < 4; mt++)
                #pragma unroll
                for (int nt = 0; nt < 4; nt++)
                    mma16816(acc[mt][nt], al[mt], bh2[nt]);
            if (mode == 0) {
                #pragma unroll
                for (int mt = 0; mt < 4; mt++)
                    #pragma unroll
                    for (int nt = 0; nt < 4; nt++)
                        mma16816(acc[mt][nt], ah[mt], bl2[nt]);
            }
        }
        __syncthreads();
        if (c + 2 < nc) load_chunk(c + 2);
    }

    if (mode == 0) {
        float* Cb = S + (size_t)z * Tt * Tt;
        #pragma unroll
        for (int mt = 0; mt < 4; mt++) {
            #pragma unroll
            for (int nt = 0; nt < 4; nt++) {
                int mbase = m0 + wm * 64 + mt * 16 + (lane >> 2);
                int nbase = n0 + wn * 32 + nt * 8 + (lane & 3) * 2;
                #pragma unroll
                for (int hrow = 0; hrow < 2; hrow++) {
                    int q = mbase + hrow * 8;
                    #pragma unroll
                    for (int jj = 0; jj < 2; jj++) {
                        int kcol = nbase + jj;
                        Cb[(size_t)q * Tt + kcol] =
                            (kcol <= q) ? acc[mt][nt][hrow * 2 + jj] * ATT_SCALE : -1e30f;
                    }
                }
            }
        }
    } else {
        int bb = z >> 3, h = z & 7;
        size_t base = (size_t)bb * Tt * Dd + (size_t)h * HDim;
        #pragma unroll
        for (int mt = 0; mt < 4; mt++) {
            #pragma unroll
            for (int nt = 0; nt < 4; nt++) {
                int mbase = m0 + wm * 64 + mt * 16 + (lane >> 2);
                int nbase = n0 + wn * 32 + nt * 8 + (lane & 3) * 2;
                #pragma unroll
                for (int hrow = 0; hrow < 2; hrow++) {
                    int t = mbase + hrow * 8;
                    #pragma unroll
                    for (int jj = 0; jj < 2; jj++) {
                        int n = nbase + jj;
                        if (n < Nb)
                            Oh[base + (size_t)t * Dd + n] =
                                __float2half(acc[mt][nt][hrow * 2 + jj]);
                    }
                }
            }
        }
    }
}

// ---------------- causal softmax: S fp32 (k<=q only) -> p fp16 hi/lo, zero tail --
__global__ void softmax_k(const float* __restrict__ S, __half* __restrict__ ph,
                          __half* __restrict__ pl) {
    int bid = blockIdx.x;
    int q = bid & (Tt - 1);
    int bh = bid >> 9;
    const float* row = S + ((size_t)bh * Tt + q) * Tt;
    int len = q + 1;
    int tid = threadIdx.x;   // 128
    float v[4];
    float mx = -1e30f;
    #pragma unroll
    for (int j = 0; j < 4; j++) {
        int kcol = j * 128 + tid;
        v[j] = (kcol < len) ? row[kcol] : -1e30f;   // never read above causal diagonal
        mx = fmaxf(mx, v[j]);
    }
    __shared__ float red[128];
    red[tid] = mx;
    __syncthreads();
    #pragma unroll
    for (int st = 64; st > 0; st >>= 1) { if (tid < st) red[tid] = fmaxf(red[tid], red[tid + st]); __syncthreads(); }
    mx = red[0];
    __syncthreads();
    float sum = 0.f;
    #pragma unroll
    for (int j = 0; j < 4; j++) {
        int kcol = j * 128 + tid;
        v[j] = (kcol < len) ? expf(v[j] - mx) : 0.f;
        sum += v[j];
    }
    red[tid] = sum;
    __syncthreads();
    #pragma unroll
    for (int st = 64; st > 0; st >>= 1) { if (tid < st) red[tid] += red[tid + st]; __syncthreads(); }
    float inv = 1.0f / red[0];
    size_t base = ((size_t)bh * Tt + q) * Tt;
    #pragma unroll
    for (int j = 0; j < 4; j++) {
        float p = v[j] * inv;                        // 0 in masked tail
        __half hp = __float2half(p);
        size_t ix = base + j * 128 + tid;
        ph[ix] = hp;
        pl[ix] = __float2half(p - __half2float(hp));
    }
}

// ---------------- launch ----------------
extern "C" void kernel_launch(void* const* d_in, const int* in_sizes, int n_in,
                              void* d_out, int out_size) {
    const int*   idx    = (const int*)  d_in[0];
    const float* tok    = (const float*)d_in[1];
    const float* pos    = (const float*)d_in[2];
    const float* ln1_s  = (const float*)d_in[3];
    const float* ln1_b  = (const float*)d_in[4];
    const float* qkv_w  = (const float*)d_in[5];
    const float* out_w  = (const float*)d_in[6];
    const float* ln2_s  = (const float*)d_in[7];
    const float* ln2_b  = (const float*)d_in[8];
    const float* ffn_w1 = (const float*)d_in[9];
    const float* ffn_b1 = (const float*)d_in[10];
    const float* ffn_w2 = (const float*)d_in[11];
    const float* ffn_b2 = (const float*)d_in[12];
    const float* fn_s   = (const float*)d_in[13];
    const float* fn_b   = (const float*)d_in[14];
    const float* head_w = (const float*)d_in[15];

    float* logits = (float*)d_out;
    float* hidden = logits + (size_t)Bz * Tt * Vv;

    float *x, *s;
    __half *h16, *f16, *qh, *ql, *kh, *kl, *vth, *ph, *pl, *oh;
    __half *wq, *wo, *w1, *w2, *wh;
    cudaGetSymbolAddress((void**)&x,   g_x);
    cudaGetSymbolAddress((void**)&s,   g_s);
    cudaGetSymbolAddress((void**)&h16, g_h16);
    cudaGetSymbolAddress((void**)&f16, g_f16);
    cudaGetSymbolAddress((void**)&qh,  g_qh);  cudaGetSymbolAddress((void**)&ql, g_ql);
    cudaGetSymbolAddress((void**)&kh,  g_kh);  cudaGetSymbolAddress((void**)&kl, g_kl);
    cudaGetSymbolAddress((void**)&vth, g_vth);
    cudaGetSymbolAddress((void**)&ph,  g_ph);  cudaGetSymbolAddress((void**)&pl, g_pl);
    cudaGetSymbolAddress((void**)&oh,  g_oh);
    cudaGetSymbolAddress((void**)&wq,  g_wq);
    cudaGetSymbolAddress((void**)&wo,  g_wo);
    cudaGetSymbolAddress((void**)&w1,  g_w1);
    cudaGetSymbolAddress((void**)&w2,  g_w2);
    cudaGetSymbolAddress((void**)&wh,  g_wh);

    cudaFuncSetAttribute(gemm_mm,  cudaFuncAttributeMaxDynamicSharedMemorySize, SMEM_MM);
    cudaFuncSetAttribute(attn_mma, cudaFuncAttributeMaxDynamicSharedMemorySize, SMEM_AT);

    {
        size_t n1 = (size_t)Ll * 3 * Dd * Dd / 4;
        size_t n2 = (size_t)Ll * Dd * Dd / 4;
        size_t n3 = (size_t)Ll * 4 * Dd * Dd / 4;
        size_t n5 = (size_t)Vv * Dd / 4;
        cvt_k<<<(unsigned)((n1 + 255) / 256), 256>>>(qkv_w,  wq, n1);
        cvt_k<<<(unsigned)((n2 + 255) / 256), 256>>>(out_w,  wo, n2);
        cvt_k<<<(unsigned)((n3 + 255) / 256), 256>>>(ffn_w1, w1, n3);
        cvt_k<<<(unsigned)((n3 + 255) / 256), 256>>>(ffn_w2, w2, n3);
        cvt_k<<<(unsigned)((n5 + 255) / 256), 256>>>(head_w, wh, n5);
    }

    embed_k<<<(MR * Dd) / 256, 256>>>(idx, tok, pos, x);

    for (int l = 0; l < Ll; l++) {
        ln_k<<<MR, 256>>>(x, ln1_s + l * Dd, ln1_b + l * Dd, h16, nullptr);
        gemm_mm<<<dim3(18, 16), 256, SMEM_MM>>>(h16, wq + (size_t)l * 3 * Dd * Dd,
                                                3 * Dd, Dd, nullptr, nullptr, nullptr, nullptr, 2, 0);
        attn_mma<<<dim3(4, 4, BH), 256, SMEM_AT>>>(qh, ql, kh, kl, s, nullptr,
                                                   HDP, Tt, (long)Tt * HDP, (long)Tt * HDP, 0);
        softmax_k<<<BH * Tt, 128>>>(s, ph, pl);
        attn_mma<<<dim3(1, 4, BH), 256, SMEM_AT>>>(ph, pl, vth, nullptr, nullptr, oh,
                                                   Tt, HDim, (long)Tt * Tt, (long)HDim * Tt, 1);
        gemm_mm<<<dim3(6, 16), 256, SMEM_MM>>>(oh, wo + (size_t)l * Dd * Dd,
                                               Dd, Dd, nullptr, x, x, nullptr, 0, 0);
        ln_k<<<MR, 256>>>(x, ln2_s + l * Dd, ln2_b + l * Dd, h16, nullptr);
        gemm_mm<<<dim3(24, 16), 256, SMEM_MM>>>(h16, w1 + (size_t)l * 4 * Dd * Dd,
                                                4 * Dd, Dd, ffn_b1 + l * 4 * Dd, nullptr,
                                                nullptr, f16, 1, 0);
        gemm_mm<<<dim3(6, 16), 256, SMEM_MM>>>(f16, w2 + (size_t)l * 4 * Dd * Dd,
                                               Dd, 4 * Dd, ffn_b2 + l * Dd, x, x, nullptr, 0, 0);
    }

    ln_k<<<MR, 256>>>(x, fn_s, fn_b, h16, hidden);
    // head GEMM: swapxy=1 so a scheduling wave shares weight tiles (B streamed once)
    gemm_mm<<<dim3(16, 393), 256, SMEM_MM>>>(h16, wh, Vv, Dd,
                                             nullptr, nullptr, logits, nullptr, 0, 1);
}

// round 10
// speedup vs baseline: 5.7491x; 1.1625x over previous
#include <cuda_runtime.h>
#include <cuda_fp16.h>
#include <math.h>
#include <stdint.h>

#define Bz   4
#define Tt   512
#define Dd   768
#define Hh   8
#define HDim 96
#define HDP  128            // padded head dim for MMA (pad cols stay zero: globals zero-init)
#define Ll   12
#define Vv   50257
#define MR   (Bz*Tt)
#define BH   (Bz*Hh)
#define ATT_SCALE 0.10206207261596575f

__device__ __forceinline__ uint32_t smem_u32(const void* p) {
    uint32_t a;
    asm("{ .reg .u64 t; cvta.to.shared.u64 t, %1; cvt.u32.u64 %0, t; }" : "=r"(a) : "l"(p));
    return a;
}

// ---------------- scratch (device globals) ----------------
__device__ float g_x [MR*Dd];
__device__ __align__(16) __half g_h16[MR*Dd];
__device__ __align__(16) __half g_f16[MR*4*Dd];
__device__ __align__(16) __half g_qh[(size_t)BH*Tt*HDP], g_ql[(size_t)BH*Tt*HDP];
__device__ __align__(16) __half g_kh[(size_t)BH*Tt*HDP], g_kl[(size_t)BH*Tt*HDP];
__device__ __align__(16) __half g_vth[(size_t)BH*HDim*Tt];
__device__ __align__(16) __half g_oh[MR*Dd];
__device__ __align__(16) __half g_wq[(size_t)Ll*3*Dd*Dd];
__device__ __align__(16) __half g_wo[(size_t)Ll*Dd*Dd];
__device__ __align__(16) __half g_w1[(size_t)Ll*4*Dd*Dd];
__device__ __align__(16) __half g_w2[(size_t)Ll*4*Dd*Dd];
__device__ __align__(16) __half g_wh[(size_t)Vv*Dd];

// ---------------- weight fp32 -> fp16 ----------------
__global__ void cvt_k(const float* __restrict__ w, __half* __restrict__ o, size_t n4) {
    size_t i = (size_t)blockIdx.x * 256 + threadIdx.x;
    if (i >= n4) return;
    float4 v = ((const float4*)w)[i];
    ((__half2*)o)[i * 2]     = __floats2half2_rn(v.x, v.y);
    ((__half2*)o)[i * 2 + 1] = __floats2half2_rn(v.z, v.w);
}

// ---------------- embedding ----------------
__global__ void embed_k(const int* __restrict__ idx, const float* __restrict__ tok,
                        const float* __restrict__ pos, float* __restrict__ x) {
    int i = blockIdx.x * 256 + threadIdx.x;
    int m = i / Dd, d = i - m * Dd;
    int t = m & (Tt - 1);
    x[i] = tok[(size_t)idx[m] * Dd + d] + pos[t * Dd + d];
}

// ---------------- layernorm -> fp16 (+ optional fp32) ----------------
__global__ void ln_k(const float* __restrict__ in, const float* __restrict__ s,
                     const float* __restrict__ b, __half* __restrict__ oh,
                     float* __restrict__ ofp) {
    int m = blockIdx.x, tid = threadIdx.x;
    const float* row = in + (size_t)m * Dd;
    float x0 = row[tid], x1 = row[tid + 256], x2 = row[tid + 512];
    __shared__ float red[256];
    red[tid] = x0 + x1 + x2;
    __syncthreads();
    #pragma unroll
    for (int st = 128; st > 0; st >>= 1) { if (tid < st) red[tid] += red[tid + st]; __syncthreads(); }
    float mean = red[0] * (1.0f / Dd);
    __syncthreads();
    float d0 = x0 - mean, d1 = x1 - mean, d2 = x2 - mean;
    red[tid] = d0 * d0 + d1 * d1 + d2 * d2;
    __syncthreads();
    #pragma unroll
    for (int st = 128; st > 0; st >>= 1) { if (tid < st) red[tid] += red[tid + st]; __syncthreads(); }
    float inv = rsqrtf(red[0] * (1.0f / Dd) + 1e-5f);
    size_t base = (size_t)m * Dd;
    #pragma unroll
    for (int q = 0; q < 3; q++) {
        int c = tid + q * 256;
        float dv = (q == 0 ? d0 : (q == 1 ? d1 : d2));
        float v = dv * inv * s[c] + b[c];
        oh[base + c] = __float2half(v);
        if (ofp) ofp[base + c] = v;
    }
}

// ---------------- HMMA primitives ----------------
__device__ __forceinline__ void ldsm4(uint32_t& r0, uint32_t& r1, uint32_t& r2, uint32_t& r3,
                                      uint32_t addr) {
    asm volatile("ldmatrix.sync.aligned.m8n8.x4.shared.b16 {%0,%1,%2,%3}, [%4];"
                 : "=r"(r0), "=r"(r1), "=r"(r2), "=r"(r3) : "r"(addr));
}
__device__ __forceinline__ void mma16816(float* d, const uint32_t* a, const uint32_t* b) {
    asm volatile("mma.sync.aligned.m16n8k16.row.col.f32.f16.f16.f32 "
                 "{%0,%1,%2,%3}, {%4,%5,%6,%7}, {%8,%9}, {%0,%1,%2,%3};"
                 : "+f"(d[0]), "+f"(d[1]), "+f"(d[2]), "+f"(d[3])
                 : "r"(a[0]), "r"(a[1]), "r"(a[2]), "r"(a[3]), "r"(b[0]), "r"(b[1]));
}

#define ROWB 144
#define OPB  (128*ROWB)
#define STG  (2*OPB)
#define SMEM_MM (2*STG)        // 73728 (2 operands, 2 stages)

// ---------------- main fp16 GEMM: C[M,N] = A[M,K]*B[N,K]^T, fp32 acc ----------
// mode: 0 normal | 1 gelu(bias) | 2 qkv split scatter (fp16 hi/lo q,k + v^T)
// swapxy: m from blockIdx.x (fast) -> concurrent CTAs share B tiles (head GEMM)
__global__ __launch_bounds__(256, 2) void gemm_mm(
    const __half* __restrict__ A, const __half* __restrict__ Bm,
    int N, int K,
    const float* __restrict__ bias, const float* __restrict__ resid,
    float* __restrict__ Cf, __half* __restrict__ Ch, int mode, int swapxy)
{
    extern __shared__ char smem[];
    uint32_t sb = smem_u32(smem);
    int tid = threadIdx.x, wid = tid >> 5, lane = tid & 31;
    int wm = wid >> 2, wn = wid & 3;
    int m0 = (swapxy ? blockIdx.x : blockIdx.y) * 128;
    int n0 = (swapxy ? blockIdx.y : blockIdx.x) * 128;

    auto load_chunk = [&](int c) {
        int kt = c << 6;
        uint32_t st = sb + (c & 1) * STG;
        #pragma unroll
        for (int o = 0; o < 8; o++) {
            int flat = o * 256 + tid;
            int op = flat >> 10, wi = flat & 1023;
            int row = wi >> 3, c16 = wi & 7;
            uint32_t dst = st + op * OPB + row * ROWB + c16 * 16;
            const __half* src;
            if (op == 0) {
                src = A + (size_t)(m0 + row) * K + kt + c16 * 8;
            } else {
                int r = n0 + row; if (r >= N) r = N - 1;
                src = Bm + (size_t)r * K + kt + c16 * 8;
            }
            asm volatile("cp.async.cg.shared.global [%0], [%1], 16;" :: "r"(dst), "l"(src));
        }
        asm volatile("cp.async.commit_group;" ::: "memory");
    };

    float acc[4][4][4] = {};
    int nc = K >> 6;

    load_chunk(0);
    load_chunk(1);

    for (int c = 0; c < nc; c++) {
        if (c + 1 < nc) asm volatile("cp.async.wait_group 1;" ::: "memory");
        else            asm volatile("cp.async.wait_group 0;" ::: "memory");
        __syncthreads();
        uint32_t st = sb + (c & 1) * STG;
        uint32_t a_row = (uint32_t)(wm * 64 + (lane & 15)) * ROWB + (lane >> 4) * 16;
        uint32_t b_row = (uint32_t)(wn * 32 + (lane & 7) + ((lane >> 4) & 1) * 8) * ROWB
                       + ((lane >> 3) & 1) * 16;
        #pragma unroll
        for (int kk = 0; kk < 4; kk++) {
            uint32_t ah[4][4], bh[4][2];
            #pragma unroll
            for (int mt = 0; mt < 4; mt++) {
                uint32_t ad = st + a_row + mt * (16 * ROWB) + kk * 32;
                ldsm4(ah[mt][0], ah[mt][1], ah[mt][2], ah[mt][3], ad);
            }
            #pragma unroll
            for (int np = 0; np < 2; np++) {
                uint32_t bd = st + OPB + b_row + np * (16 * ROWB) + kk * 32;
                ldsm4(bh[np*2][0], bh[np*2][1], bh[np*2+1][0], bh[np*2+1][1], bd);
            }
            #pragma unroll
            for (int mt = 0; mt < 4; mt++)
                #pragma unroll
                for (int nt = 0; nt < 4; nt++)
                    mma16816(acc[mt][nt], ah[mt], bh[nt]);
        }
        __syncthreads();
        if (c + 2 < nc) load_chunk(c + 2);
    }

    #pragma unroll
    for (int mt = 0; mt < 4; mt++) {
        #pragma unroll
        for (int nt = 0; nt < 4; nt++) {
            int mbase = m0 + wm * 64 + mt * 16 + (lane >> 2);
            int nbase = n0 + wn * 32 + nt * 8 + (lane & 3) * 2;
            #pragma unroll
            for (int hrow = 0; hrow < 2; hrow++) {
                int m = mbase + hrow * 8;
                #pragma unroll
                for (int jj = 0; jj < 2; jj++) {
                    int n = nbase + jj;
                    float v = acc[mt][nt][hrow * 2 + jj];
                    if (mode == 2) {
                        int sct = n / Dd, r = n - sct * Dd;
                        int h = r / HDim, hd = r - h * HDim;
                        int bb = m >> 9, t = m & (Tt - 1);
                        int bh_ = bb * Hh + h;
                        if (sct == 0) {
                            size_t ix = ((size_t)bh_ * Tt + t) * HDP + hd;
                            __half hv = __float2half(v);
                            g_qh[ix] = hv;
                            g_ql[ix] = __float2half(v - __half2float(hv));
                        } else if (sct == 1) {
                            size_t ix = ((size_t)bh_ * Tt + t) * HDP + hd;
                            __half hv = __float2half(v);
                            g_kh[ix] = hv;
                            g_kl[ix] = __float2half(v - __half2float(hv));
                        } else {
                            g_vth[((size_t)bh_ * HDim + hd) * Tt + t] = __float2half(v);
                        }
                    } else if (n < N) {
                        if (bias) v += bias[n];
                        if (mode == 1) v = 0.5f * v * (1.0f + erff(v * 0.70710678118654752f));
                        size_t ix = (size_t)m * N + n;
                        if (resid) v += resid[ix];
                        if (Cf) Cf[ix] = v;
                        if (Ch) Ch[ix] = __float2half(v);
                    }
                }
            }
        }
    }
}

// ---------------- fused flash attention ----------------
// CTA = (m-tile of 128, head z). 8 warps x 16 rows. K/V tiles of 64, double-buffered.
// Scores: 3-pass hi/lo split (qh*kh + ql*kh + qh*kl), fp32 online softmax,
// p rounded to fp16 for PV (single pass). O -> fp16 [B,T,D].
// Row strides: Q/K rows are HDP=128 halfs = 256 B -> stride 272 (16B pad);
// V rows are 64 halfs = 128 B -> stride 144.
#define QROWB 272
#define VROWB 144
#define FQ_OP (128*QROWB)            // 34816
#define FK_OP (64*QROWB)             // 17408
#define FV_OP (96*VROWB)             // 13824
#define FSTGB (2*FK_OP + FV_OP)      // 48640
#define SMEM_FA (2*FQ_OP + 2*FSTGB)  // 166912

__global__ __launch_bounds__(256, 1) void flash_attn(
    const __half* __restrict__ Qh, const __half* __restrict__ Ql,
    const __half* __restrict__ Kh, const __half* __restrict__ Kl,
    const __half* __restrict__ Vt, __half* __restrict__ Oo)
{
    extern __shared__ char smem[];
    uint32_t sb = smem_u32(smem);
    int tid = threadIdx.x, wid = tid >> 5, lane = tid & 31;
    int mt = blockIdx.x, z = blockIdx.y;
    int m0 = mt * 128;
    int niter = 2 * (mt + 1);

    const __half* qhp = Qh + (size_t)z * Tt * HDP;
    const __half* qlp = Ql + (size_t)z * Tt * HDP;
    const __half* khp = Kh + (size_t)z * Tt * HDP;
    const __half* klp = Kl + (size_t)z * Tt * HDP;
    const __half* vtp = Vt + (size_t)z * HDim * Tt;

    // load Q hi+lo once: 2 x 128 rows x 16 x 16B = 4096 transfers
    #pragma unroll
    for (int u0 = 0; u0 < 16; u0++) {
        int u = u0 * 256 + tid;
        int hi = (u < 2048);
        int v = u & 2047;
        int row = v >> 4, c16 = v & 15;
        uint32_t dst = sb + (hi ? 0 : FQ_OP) + row * QROWB + c16 * 16;
        const __half* src = (hi ? qhp : qlp) + (size_t)(m0 + row) * HDP + c16 * 8;
        asm volatile("cp.async.cg.shared.global [%0], [%1], 16;" :: "r"(dst), "l"(src));
    }
    asm volatile("cp.async.commit_group;" ::: "memory");

    // K hi (1024) + K lo (1024) + V (96 rows x 8 x 16B = 768) = 2816 transfers
    auto load_kv = [&](int i) {
        int k0 = i * 64;
        uint32_t st = sb + 2 * FQ_OP + (i & 1) * FSTGB;
        #pragma unroll
        for (int u0 = 0; u0 < 11; u0++) {
            int u = u0 * 256 + tid;
            if (u < 2048) {
                int hi = (u < 1024);
                int v = u & 1023;
                int row = v >> 4, c16 = v & 15;
                uint32_t dst = st + (hi ? 0 : FK_OP) + row * QROWB + c16 * 16;
                const __half* src = (hi ? khp : klp) + (size_t)(k0 + row) * HDP + c16 * 8;
                asm volatile("cp.async.cg.shared.global [%0], [%1], 16;" :: "r"(dst), "l"(src));
            } else {
                int v = u - 2048;           // [0, 768)
                int row = v >> 3, c16 = v & 7;
                uint32_t dst = st + 2 * FK_OP + row * VROWB + c16 * 16;
                const __half* src = vtp + (size_t)row * Tt + k0 + c16 * 8;
                asm volatile("cp.async.cg.shared.global [%0], [%1], 16;" :: "r"(dst), "l"(src));
            }
        }
        asm volatile("cp.async.commit_group;" ::: "memory");
    };

    load_kv(0);
    load_kv(1);

    float o[12][4] = {};
    float m_r = -1e30f, m_r8 = -1e30f, l_r = 0.f, l_r8 = 0.f;
    int qrow = m0 + wid * 16 + (lane >> 2);   // rows for c0,c1 ; c2,c3 -> qrow+8

    for (int i = 0; i < niter; i++) {
        if (i + 1 < niter) asm volatile("cp.async.wait_group 1;" ::: "memory");
        else               asm volatile("cp.async.wait_group 0;" ::: "memory");
        __syncthreads();
        uint32_t st = sb + 2 * FQ_OP + (i & 1) * FSTGB;
        int k0 = i * 64;

        // scores: S[16x64] = Q[16x128] * K[64x128]^T (3 passes)
        float sacc[8][4] = {};
        uint32_t aqbase = sb + (uint32_t)(wid * 16 + (lane & 15)) * QROWB + (lane >> 4) * 16;
        uint32_t bkbase = st + (uint32_t)((lane & 7) + ((lane >> 4) & 1) * 8) * QROWB
                        + ((lane >> 3) & 1) * 16;
        #pragma unroll
        for (int kk = 0; kk < 8; kk++) {
            uint32_t ah[4], al[4];
            ldsm4(ah[0], ah[1], ah[2], ah[3], aqbase + kk * 32);
            ldsm4(al[0], al[1], al[2], al[3], aqbase + FQ_OP + kk * 32);
            #pragma unroll
            for (int np = 0; np < 4; np++) {
                uint32_t bh0[2], bh1[2], bl0[2], bl1[2];
                uint32_t bd = bkbase + np * (16 * QROWB) + kk * 32;
                ldsm4(bh0[0], bh0[1], bh1[0], bh1[1], bd);
                ldsm4(bl0[0], bl0[1], bl1[0], bl1[1], bd + FK_OP);
                mma16816(sacc[np*2],   ah, bh0);
                mma16816(sacc[np*2+1], ah, bh1);
                mma16816(sacc[np*2],   al, bh0);
                mma16816(sacc[np*2+1], al, bh1);
                mma16816(sacc[np*2],   ah, bl0);
                mma16816(sacc[np*2+1], ah, bl1);
            }
        }

        // scale + causal mask + tile max
        float tmax_r = -1e30f, tmax_r8 = -1e30f;
        #pragma unroll
        for (int t = 0; t < 8; t++) {
            #pragma unroll
            for (int jj = 0; jj < 2; jj++) {
                int kcol = k0 + t * 8 + (lane & 3) * 2 + jj;
                float s0 = (kcol <= qrow)     ? sacc[t][jj]     * ATT_SCALE : -1e30f;
                float s1 = (kcol <= qrow + 8) ? sacc[t][2 + jj] * ATT_SCALE : -1e30f;
                sacc[t][jj] = s0; sacc[t][2 + jj] = s1;
                tmax_r  = fmaxf(tmax_r, s0);
                tmax_r8 = fmaxf(tmax_r8, s1);
            }
        }
        tmax_r  = fmaxf(tmax_r,  __shfl_xor_sync(0xffffffffu, tmax_r, 1));
        tmax_r  = fmaxf(tmax_r,  __shfl_xor_sync(0xffffffffu, tmax_r, 2));
        tmax_r8 = fmaxf(tmax_r8, __shfl_xor_sync(0xffffffffu, tmax_r8, 1));
        tmax_r8 = fmaxf(tmax_r8, __shfl_xor_sync(0xffffffffu, tmax_r8, 2));
        float mn_r = fmaxf(m_r, tmax_r), mn_r8 = fmaxf(m_r8, tmax_r8);
        float f_r = __expf(m_r - mn_r), f_r8 = __expf(m_r8 - mn_r8);
        m_r = mn_r; m_r8 = mn_r8;

        // p = exp(s - m), pack to fp16 A-fragments, accumulate row sums
        uint32_t pr[8], pr8[8];
        float ls_r = 0.f, ls_r8 = 0.f;
        #pragma unroll
        for (int t = 0; t < 8; t++) {
            float p0 = __expf(sacc[t][0] - m_r);
            float p1 = __expf(sacc[t][1] - m_r);
            float p2 = __expf(sacc[t][2] - m_r8);
            float p3 = __expf(sacc[t][3] - m_r8);
            ls_r += p0 + p1; ls_r8 += p2 + p3;
            __half2 h01 = __floats2half2_rn(p0, p1);
            __half2 h23 = __floats2half2_rn(p2, p3);
            pr[t]  = *(uint32_t*)&h01;
            pr8[t] = *(uint32_t*)&h23;
        }
        ls_r  += __shfl_xor_sync(0xffffffffu, ls_r, 1);
        ls_r  += __shfl_xor_sync(0xffffffffu, ls_r, 2);
        ls_r8 += __shfl_xor_sync(0xffffffffu, ls_r8, 1);
        ls_r8 += __shfl_xor_sync(0xffffffffu, ls_r8, 2);
        l_r  = l_r  * f_r  + ls_r;
        l_r8 = l_r8 * f_r8 + ls_r8;
        #pragma unroll
        for (int t = 0; t < 12; t++) {
            o[t][0] *= f_r;  o[t][1] *= f_r;
            o[t][2] *= f_r8; o[t][3] *= f_r8;
        }

        // O += P[16x64] * V[64x96]
        uint32_t bvbase = st + 2 * FK_OP
                        + (uint32_t)((lane & 7) + ((lane >> 4) & 1) * 8) * VROWB
                        + ((lane >> 3) & 1) * 16;
        #pragma unroll
        for (int j = 0; j < 4; j++) {
            uint32_t a[4] = { pr[2*j], pr8[2*j], pr[2*j+1], pr8[2*j+1] };
            #pragma unroll
            for (int np = 0; np < 6; np++) {
                uint32_t bv0[2], bv1[2];
                ldsm4(bv0[0], bv0[1], bv1[0], bv1[1], bvbase + np * (16 * VROWB) + j * 32);
                mma16816(o[np*2],   a, bv0);
                mma16816(o[np*2+1], a, bv1);
            }
        }
        __syncthreads();
        if (i + 2 < niter) load_kv(i + 2);
    }

    float inv_r = 1.f / l_r, inv_r8 = 1.f / l_r8;
    int bb = z >> 3, h = z & 7;
    size_t base = (size_t)bb * Tt * Dd + (size_t)h * HDim;
    #pragma unroll
    for (int t = 0; t < 12; t++) {
        int n = t * 8 + (lane & 3) * 2;
        size_t ixr  = base + (size_t)qrow * Dd + n;
        size_t ixr8 = base + (size_t)(qrow + 8) * Dd + n;
        Oo[ixr]      = __float2half(o[t][0] * inv_r);
        Oo[ixr + 1]  = __float2half(o[t][1] * inv_r);
        Oo[ixr8]     = __float2half(o[t][2] * inv_r8);
        Oo[ixr8 + 1] = __float2half(o[t][3] * inv_r8);
    }
}

// ---------------- launch ----------------
extern "C" void kernel_launch(void* const* d_in, const int* in_sizes, int n_in,
                              void* d_out, int out_size) {
    const int*   idx    = (const int*)  d_in[0];
    const float* tok    = (const float*)d_in[1];
    const float* pos    = (const float*)d_in[2];
    const float* ln1_s  = (const float*)d_in[3];
    const float* ln1_b  = (const float*)d_in[4];
    const float* qkv_w  = (const float*)d_in[5];
    const float* out_w  = (const float*)d_in[6];
    const float* ln2_s  = (const float*)d_in[7];
    const float* ln2_b  = (const float*)d_in[8];
    const float* ffn_w1 = (const float*)d_in[9];
    const float* ffn_b1 = (const float*)d_in[10];
    const float* ffn_w2 = (const float*)d_in[11];
    const float* ffn_b2 = (const float*)d_in[12];
    const float* fn_s   = (const float*)d_in[13];
    const float* fn_b   = (const float*)d_in[14];
    const float* head_w = (const float*)d_in[15];

    float* logits = (float*)d_out;
    float* hidden = logits + (size_t)Bz * Tt * Vv;

    float *x;
    __half *h16, *f16, *qh, *ql, *kh, *kl, *vth, *oh;
    __half *wq, *wo, *w1, *w2, *wh;
    cudaGetSymbolAddress((void**)&x,   g_x);
    cudaGetSymbolAddress((void**)&h16, g_h16);
    cudaGetSymbolAddress((void**)&f16, g_f16);
    cudaGetSymbolAddress((void**)&qh,  g_qh);  cudaGetSymbolAddress((void**)&ql, g_ql);
    cudaGetSymbolAddress((void**)&kh,  g_kh);  cudaGetSymbolAddress((void**)&kl, g_kl);
    cudaGetSymbolAddress((void**)&vth, g_vth);
    cudaGetSymbolAddress((void**)&oh,  g_oh);
    cudaGetSymbolAddress((void**)&wq,  g_wq);
    cudaGetSymbolAddress((void**)&wo,  g_wo);
    cudaGetSymbolAddress((void**)&w1,  g_w1);
    cudaGetSymbolAddress((void**)&w2,  g_w2);
    cudaGetSymbolAddress((void**)&wh,  g_wh);

    cudaFuncSetAttribute(gemm_mm,    cudaFuncAttributeMaxDynamicSharedMemorySize, SMEM_MM);
    cudaFuncSetAttribute(flash_attn, cudaFuncAttributeMaxDynamicSharedMemorySize, SMEM_FA);

    {
        size_t n1 = (size_t)Ll * 3 * Dd * Dd / 4;
        size_t n2 = (size_t)Ll * Dd * Dd / 4;
        size_t n3 = (size_t)Ll * 4 * Dd * Dd / 4;
        size_t n5 = (size_t)Vv * Dd / 4;
        cvt_k<<<(unsigned)((n1 + 255) / 256), 256>>>(qkv_w,  wq, n1);
        cvt_k<<<(unsigned)((n2 + 255) / 256), 256>>>(out_w,  wo, n2);
        cvt_k<<<(unsigned)((n3 + 255) / 256), 256>>>(ffn_w1, w1, n3);
        cvt_k<<<(unsigned)((n3 + 255) / 256), 256>>>(ffn_w2, w2, n3);
        cvt_k<<<(unsigned)((n5 + 255) / 256), 256>>>(head_w, wh, n5);
    }

    embed_k<<<(MR * Dd) / 256, 256>>>(idx, tok, pos, x);

    for (int l = 0; l < Ll; l++) {
        ln_k<<<MR, 256>>>(x, ln1_s + l * Dd, ln1_b + l * Dd, h16, nullptr);
        gemm_mm<<<dim3(18, 16), 256, SMEM_MM>>>(h16, wq + (size_t)l * 3 * Dd * Dd,
                                                3 * Dd, Dd, nullptr, nullptr, nullptr, nullptr, 2, 0);
        flash_attn<<<dim3(4, BH), 256, SMEM_FA>>>(qh, ql, kh, kl, vth, oh);
        gemm_mm<<<dim3(6, 16), 256, SMEM_MM>>>(oh, wo + (size_t)l * Dd * Dd,
                                               Dd, Dd, nullptr, x, x, nullptr, 0, 0);
        ln_k<<<MR, 256>>>(x, ln2_s + l * Dd, ln2_b + l * Dd, h16, nullptr);
        gemm_mm<<<dim3(24, 16), 256, SMEM_MM>>>(h16, w1 + (size_t)l * 4 * Dd * Dd,
                                                4 * Dd, Dd, ffn_b1 + l * 4 * Dd, nullptr,
                                                nullptr, f16, 1, 0);
        gemm_mm<<<dim3(6, 16), 256, SMEM_MM>>>(f16, w2 + (size_t)l * 4 * Dd * Dd,
                                               Dd, 4 * Dd, ffn_b2 + l * Dd, x, x, nullptr, 0, 0);
    }

    ln_k<<<MR, 256>>>(x, fn_s, fn_b, h16, hidden);
    // head GEMM: swapxy=1 so a scheduling wave shares weight tiles (B streamed once)
    gemm_mm<<<dim3(16, 393), 256, SMEM_MM>>>(h16, wh, Vv, Dd,
                                             nullptr, nullptr, logits, nullptr, 0, 1);
}